// round 1
// baseline (speedup 1.0000x reference)
#include <cuda_runtime.h>
#include <math.h>

// ---------------- Problem constants ----------------
#define B_   32
#define S_   197
#define NP_  196
#define D_   768
#define FF_  3072
#define L_   12
#define NH_  12
#define HD_  64
#define NC_  1000
#define M_   (B_ * S_)    // 6304
#define MP_  (B_ * NP_)   // 6272
#define EPS_ 1e-5f

// ---------------- Scratch (device globals; no allocs allowed) ----------------
__device__ float g_patches[(size_t)MP_ * D_];
__device__ float g_hp[(size_t)MP_ * D_];
__device__ float g_h[(size_t)M_ * D_];
__device__ float g_z[(size_t)M_ * D_];
__device__ float g_q[(size_t)M_ * D_];
__device__ float g_k[(size_t)M_ * D_];
__device__ float g_v[(size_t)M_ * D_];
__device__ float g_y[(size_t)M_ * D_];
__device__ float g_scores[(size_t)B_ * NH_ * S_ * S_];
__device__ float g_mlp[(size_t)M_ * FF_];
__device__ float g_cls[B_ * D_];
__device__ float g_clsln[B_ * D_];

// ---------------- Helpers ----------------
__device__ __forceinline__ float gelu_exact(float x) {
    return 0.5f * x * (1.0f + erff(x * 0.70710678118654752440f));
}

__device__ __forceinline__ float blockReduceSum256(float v) {
    __shared__ float sh[8];
    int lane = threadIdx.x & 31, wid = threadIdx.x >> 5;
#pragma unroll
    for (int o = 16; o > 0; o >>= 1) v += __shfl_down_sync(0xffffffffu, v, o);
    if (lane == 0) sh[wid] = v;
    __syncthreads();
    if (wid == 0) {
        v = (lane < 8) ? sh[lane] : 0.0f;
#pragma unroll
        for (int o = 4; o > 0; o >>= 1) v += __shfl_down_sync(0xffffffffu, v, o);
        if (lane == 0) sh[0] = v;
    }
    __syncthreads();
    float r = sh[0];
    __syncthreads();
    return r;
}

__device__ __forceinline__ float blockReduceMax256(float v) {
    __shared__ float sh[8];
    int lane = threadIdx.x & 31, wid = threadIdx.x >> 5;
#pragma unroll
    for (int o = 16; o > 0; o >>= 1) v = fmaxf(v, __shfl_down_sync(0xffffffffu, v, o));
    if (lane == 0) sh[wid] = v;
    __syncthreads();
    if (wid == 0) {
        v = (lane < 8) ? sh[lane] : -3.0e38f;
#pragma unroll
        for (int o = 4; o > 0; o >>= 1) v = fmaxf(v, __shfl_down_sync(0xffffffffu, v, o));
        if (lane == 0) sh[0] = v;
    }
    __syncthreads();
    float r = sh[0];
    __syncthreads();
    return r;
}

// ---------------- SGEMM: C[M,N] = A[M,K] @ B[K,N] + bias (+gelu) (+res) ----------------
// 128x128 tile, BK=8, 256 threads, 8x8 per thread. K must be a multiple of 8,
// A rows 16B-aligned (K % 4 == 0), B cols 16B-stride-aligned (N % 4 == 0).
__global__ __launch_bounds__(256) void sgemm128(
    const float* __restrict__ A, const float* __restrict__ Bm,
    const float* __restrict__ bias, const float* __restrict__ res,
    float* __restrict__ C, int M, int N, int K, int dogelu)
{
    __shared__ float As[8][128];
    __shared__ float Bs[8][128];

    int tid = threadIdx.x;
    int tx = tid & 15, ty = tid >> 4;
    int n0 = blockIdx.x * 128, m0 = blockIdx.y * 128;

    float acc[8][8];
#pragma unroll
    for (int i = 0; i < 8; i++)
#pragma unroll
        for (int j = 0; j < 8; j++) acc[i][j] = 0.0f;

    int arow = tid >> 1, acol = (tid & 1) * 4;   // A: 128 rows x 8 cols, one float4/thread
    int brow = tid >> 5, bcol = (tid & 31) * 4;  // B: 8 rows x 128 cols, one float4/thread

    for (int k0 = 0; k0 < K; k0 += 8) {
        float4 av = make_float4(0.f, 0.f, 0.f, 0.f);
        if (m0 + arow < M)
            av = *reinterpret_cast<const float4*>(A + (size_t)(m0 + arow) * K + k0 + acol);
        As[acol + 0][arow] = av.x;
        As[acol + 1][arow] = av.y;
        As[acol + 2][arow] = av.z;
        As[acol + 3][arow] = av.w;

        float4 bv;
        int gn = n0 + bcol;
        const float* brp = Bm + (size_t)(k0 + brow) * N;
        if (gn + 3 < N) {
            bv = *reinterpret_cast<const float4*>(brp + gn);
        } else {
            bv.x = (gn + 0 < N) ? brp[gn + 0] : 0.f;
            bv.y = (gn + 1 < N) ? brp[gn + 1] : 0.f;
            bv.z = (gn + 2 < N) ? brp[gn + 2] : 0.f;
            bv.w = (gn + 3 < N) ? brp[gn + 3] : 0.f;
        }
        *reinterpret_cast<float4*>(&Bs[brow][bcol]) = bv;

        __syncthreads();

#pragma unroll
        for (int kk = 0; kk < 8; kk++) {
            float a[8], b[8];
            *reinterpret_cast<float4*>(&a[0]) = *reinterpret_cast<const float4*>(&As[kk][ty * 8]);
            *reinterpret_cast<float4*>(&a[4]) = *reinterpret_cast<const float4*>(&As[kk][ty * 8 + 4]);
            *reinterpret_cast<float4*>(&b[0]) = *reinterpret_cast<const float4*>(&Bs[kk][tx * 8]);
            *reinterpret_cast<float4*>(&b[4]) = *reinterpret_cast<const float4*>(&Bs[kk][tx * 8 + 4]);
#pragma unroll
            for (int i = 0; i < 8; i++)
#pragma unroll
                for (int j = 0; j < 8; j++) acc[i][j] = fmaf(a[i], b[j], acc[i][j]);
        }
        __syncthreads();
    }

#pragma unroll
    for (int i = 0; i < 8; i++) {
        int m = m0 + ty * 8 + i;
        if (m >= M) continue;
#pragma unroll
        for (int j = 0; j < 8; j++) {
            int n = n0 + tx * 8 + j;
            if (n >= N) continue;
            float vv = acc[i][j] + bias[n];
            if (dogelu) vv = gelu_exact(vv);
            if (res) vv += res[(size_t)m * N + n];
            C[(size_t)m * N + n] = vv;
        }
    }
}

// ---------------- LayerNorm: out = (x-mean)/(sqrt(var)+eps)*w + b ----------------
__global__ __launch_bounds__(256) void ln_kernel(
    const float* __restrict__ x, const float* __restrict__ w,
    const float* __restrict__ b, float* __restrict__ out)
{
    __shared__ float row[D_];
    int m = blockIdx.x;
    const float* xr = x + (size_t)m * D_;
    float s = 0.0f;
    for (int d = threadIdx.x; d < D_; d += 256) {
        float v = xr[d];
        row[d] = v;
        s += v;
    }
    __syncthreads();
    s = blockReduceSum256(s);
    float mean = s * (1.0f / D_);
    float s2 = 0.0f;
    for (int d = threadIdx.x; d < D_; d += 256) {
        float v = row[d] - mean;
        s2 += v * v;
    }
    s2 = blockReduceSum256(s2);
    float inv = 1.0f / (sqrtf(s2 * (1.0f / D_)) + EPS_);
    float* op = out + (size_t)m * D_;
    for (int d = threadIdx.x; d < D_; d += 256)
        op[d] = (row[d] - mean) * inv * w[d] + b[d];
}

// ---------------- Attention: scores = Q K^T / 8 ----------------
__global__ __launch_bounds__(256) void scores_kernel(
    const float* __restrict__ q, const float* __restrict__ k, float* __restrict__ s)
{
    __shared__ float Qs[16][68];
    __shared__ float Ks[16][68];
    int bh = blockIdx.z;
    int b = bh / NH_, h = bh % NH_;
    int i0 = blockIdx.y * 16, j0 = blockIdx.x * 16;
    int t = threadIdx.x;
    int r = t >> 4, c = (t & 15) * 4;

    float4 qv = make_float4(0.f, 0.f, 0.f, 0.f);
    if (i0 + r < S_)
        qv = *reinterpret_cast<const float4*>(q + (size_t)(b * S_ + i0 + r) * D_ + h * HD_ + c);
    *reinterpret_cast<float4*>(&Qs[r][c]) = qv;

    float4 kv = make_float4(0.f, 0.f, 0.f, 0.f);
    if (j0 + r < S_)
        kv = *reinterpret_cast<const float4*>(k + (size_t)(b * S_ + j0 + r) * D_ + h * HD_ + c);
    *reinterpret_cast<float4*>(&Ks[r][c]) = kv;

    __syncthreads();

    int ty = t >> 4, tx = t & 15;
    float acc = 0.0f;
#pragma unroll
    for (int cc = 0; cc < HD_; cc++) acc = fmaf(Qs[ty][cc], Ks[tx][cc], acc);

    int i = i0 + ty, j = j0 + tx;
    if (i < S_ && j < S_)
        s[((size_t)bh * S_ + i) * S_ + j] = acc * 0.125f;
}

// ---------------- Softmax over last dim (len 197) ----------------
__global__ __launch_bounds__(256) void softmax_kernel(float* __restrict__ s)
{
    int r = blockIdx.x;
    float* p = s + (size_t)r * S_;
    int t = threadIdx.x;
    float v = (t < S_) ? p[t] : -3.0e38f;
    float mx = blockReduceMax256(v);
    float e = (t < S_) ? expf(v - mx) : 0.0f;
    float sum = blockReduceSum256(e);
    if (t < S_) p[t] = e / sum;
}

// ---------------- y = attn @ V (merge heads into [B*S, D]) ----------------
__global__ __launch_bounds__(256) void av_kernel(
    const float* __restrict__ att, const float* __restrict__ v, float* __restrict__ y)
{
    __shared__ float As[16][17];
    __shared__ float Vs[16][68];
    int bh = blockIdx.y;
    int b = bh / NH_, h = bh % NH_;
    int i0 = blockIdx.x * 16;
    int t = threadIdx.x;
    int tx = t & 15, ty = t >> 4;

    float a0 = 0.f, a1 = 0.f, a2 = 0.f, a3 = 0.f;
    for (int j0 = 0; j0 < S_; j0 += 16) {
        int i = i0 + ty, j = j0 + tx;
        As[ty][tx] = (i < S_ && j < S_) ? att[((size_t)bh * S_ + i) * S_ + j] : 0.0f;

        int r = t >> 4, c = (t & 15) * 4;
        float4 vv = make_float4(0.f, 0.f, 0.f, 0.f);
        if (j0 + r < S_)
            vv = *reinterpret_cast<const float4*>(v + (size_t)(b * S_ + j0 + r) * D_ + h * HD_ + c);
        *reinterpret_cast<float4*>(&Vs[r][c]) = vv;

        __syncthreads();
#pragma unroll
        for (int jj = 0; jj < 16; jj++) {
            float a = As[ty][jj];
            a0 = fmaf(a, Vs[jj][tx], a0);
            a1 = fmaf(a, Vs[jj][tx + 16], a1);
            a2 = fmaf(a, Vs[jj][tx + 32], a2);
            a3 = fmaf(a, Vs[jj][tx + 48], a3);
        }
        __syncthreads();
    }
    int i = i0 + ty;
    if (i < S_) {
        float* yp = y + (size_t)(b * S_ + i) * D_ + h * HD_;
        yp[tx] = a0;
        yp[tx + 16] = a1;
        yp[tx + 32] = a2;
        yp[tx + 48] = a3;
    }
}

// ---------------- Patch gather: x[B,3,224,224] -> patches[B*196, 768] ----------------
__global__ void patch_gather(const float* __restrict__ x)
{
    int idx = blockIdx.x * blockDim.x + threadIdx.x;
    if (idx >= MP_ * D_) return;
    int r = idx / D_, kk = idx - r * D_;
    int b = r / NP_, p = r - b * NP_;
    int ph = p / 14, pw = p - ph * 14;
    int c = kk >> 8;
    int rem = kk & 255;
    int pi = rem >> 4, pj = rem & 15;
    g_patches[idx] = x[((size_t)(b * 3 + c) * 224 + ph * 16 + pi) * 224 + pw * 16 + pj];
}

// ---------------- Assemble h: cls token + patch embeds + pos_emb ----------------
__global__ void assemble(const float* __restrict__ cls_token, const float* __restrict__ pos)
{
    int idx = blockIdx.x * blockDim.x + threadIdx.x;
    if (idx >= M_ * D_) return;
    int m = idx / D_, d = idx - m * D_;
    int b = m / S_, s = m - b * S_;
    float val;
    if (s == 0)
        val = cls_token[d] + pos[d];
    else
        val = g_hp[((size_t)b * NP_ + (s - 1)) * D_ + d] + pos[(size_t)s * D_ + d];
    g_h[idx] = val;
}

// ---------------- Extract CLS rows ----------------
__global__ void cls_extract()
{
    int idx = blockIdx.x * blockDim.x + threadIdx.x;
    if (idx >= B_ * D_) return;
    int b = idx / D_, d = idx - b * D_;
    g_cls[idx] = g_h[((size_t)b * S_) * D_ + d];
}

// ---------------- Host orchestration ----------------
extern "C" void kernel_launch(void* const* d_in, const int* in_sizes, int n_in,
                              void* d_out, int out_size)
{
    (void)in_sizes; (void)n_in; (void)out_size;
    const float* x         = (const float*)d_in[0];
    const float* patch_w   = (const float*)d_in[1];
    const float* patch_b   = (const float*)d_in[2];
    const float* cls_token = (const float*)d_in[3];
    const float* pos_emb   = (const float*)d_in[4];
    const float* ln1_w     = (const float*)d_in[5];
    const float* ln1_b     = (const float*)d_in[6];
    const float* wq        = (const float*)d_in[7];
    const float* bq        = (const float*)d_in[8];
    const float* wk        = (const float*)d_in[9];
    const float* bk        = (const float*)d_in[10];
    const float* wv        = (const float*)d_in[11];
    const float* bv        = (const float*)d_in[12];
    const float* wy        = (const float*)d_in[13];
    const float* by        = (const float*)d_in[14];
    const float* ln2_w     = (const float*)d_in[15];
    const float* ln2_b     = (const float*)d_in[16];
    const float* m1w       = (const float*)d_in[17];
    const float* m1b       = (const float*)d_in[18];
    const float* m2w       = (const float*)d_in[19];
    const float* m2b       = (const float*)d_in[20];
    const float* hlnw      = (const float*)d_in[21];
    const float* hlnb      = (const float*)d_in[22];
    const float* hw        = (const float*)d_in[23];
    const float* hb        = (const float*)d_in[24];
    float* out = (float*)d_out;

    float *patches, *hp, *h, *z, *q, *k, *v, *y, *sc, *mlp, *cls, *clsln;
    cudaGetSymbolAddress((void**)&patches, g_patches);
    cudaGetSymbolAddress((void**)&hp, g_hp);
    cudaGetSymbolAddress((void**)&h, g_h);
    cudaGetSymbolAddress((void**)&z, g_z);
    cudaGetSymbolAddress((void**)&q, g_q);
    cudaGetSymbolAddress((void**)&k, g_k);
    cudaGetSymbolAddress((void**)&v, g_v);
    cudaGetSymbolAddress((void**)&y, g_y);
    cudaGetSymbolAddress((void**)&sc, g_scores);
    cudaGetSymbolAddress((void**)&mlp, g_mlp);
    cudaGetSymbolAddress((void**)&cls, g_cls);
    cudaGetSymbolAddress((void**)&clsln, g_clsln);

    auto gemm = [&](const float* A, const float* Bm, const float* bias, const float* res,
                    float* C, int M, int N, int K, int dogelu) {
        dim3 g((N + 127) / 128, (M + 127) / 128);
        sgemm128<<<g, 256>>>(A, Bm, bias, res, C, M, N, K, dogelu);
    };

    // Patch embedding
    patch_gather<<<(MP_ * D_ + 255) / 256, 256>>>(x);
    gemm(patches, patch_w, patch_b, nullptr, hp, MP_, D_, D_, 0);
    assemble<<<(M_ * D_ + 255) / 256, 256>>>(cls_token, pos_emb);

    // Transformer blocks
    for (int l = 0; l < L_; l++) {
        const size_t wo = (size_t)l * D_ * D_;
        const size_t bo = (size_t)l * D_;

        ln_kernel<<<M_, 256>>>(h, ln1_w + bo, ln1_b + bo, z);
        gemm(z, wq + wo, bq + bo, nullptr, q, M_, D_, D_, 0);
        gemm(z, wk + wo, bk + bo, nullptr, k, M_, D_, D_, 0);
        gemm(z, wv + wo, bv + bo, nullptr, v, M_, D_, D_, 0);

        dim3 gs((S_ + 15) / 16, (S_ + 15) / 16, B_ * NH_);
        scores_kernel<<<gs, 256>>>(q, k, sc);
        softmax_kernel<<<B_ * NH_ * S_, 256>>>(sc);
        dim3 ga((S_ + 15) / 16, B_ * NH_);
        av_kernel<<<ga, 256>>>(sc, v, y);

        gemm(y, wy + wo, by + bo, h, h, M_, D_, D_, 0);  // residual 1 (in-place)

        ln_kernel<<<M_, 256>>>(h, ln2_w + bo, ln2_b + bo, z);
        gemm(z, m1w + (size_t)l * D_ * FF_, m1b + (size_t)l * FF_, nullptr, mlp, M_, FF_, D_, 1);
        gemm(mlp, m2w + (size_t)l * FF_ * D_, m2b + bo, h, h, M_, D_, FF_, 0);  // residual 2
    }

    // Head
    cls_extract<<<(B_ * D_ + 255) / 256, 256>>>();
    ln_kernel<<<B_, 256>>>(cls, hlnw, hlnb, clsln);
    gemm(clsln, hw, hb, nullptr, out, B_, NC_, D_, 0);
}

// round 2
// speedup vs baseline: 2.2348x; 2.2348x over previous
#include <cuda_runtime.h>
#include <math.h>

// ---------------- Problem constants ----------------
#define B_   32
#define S_   197
#define NP_  196
#define D_   768
#define FF_  3072
#define L_   12
#define NH_  12
#define HD_  64
#define NC_  1000
#define M_   (B_ * S_)    // 6304
#define MP_  (B_ * NP_)   // 6272
#define EPS_ 1e-5f

// ---------------- Scratch (device globals; no allocs allowed) ----------------
__device__ float g_patches[(size_t)MP_ * D_];
__device__ float g_hp[(size_t)MP_ * D_];
__device__ float g_h[(size_t)M_ * D_];
__device__ float g_z[(size_t)M_ * D_];
__device__ float g_q[(size_t)M_ * D_];
__device__ float g_k[(size_t)M_ * D_];
__device__ float g_v[(size_t)M_ * D_];
__device__ float g_y[(size_t)M_ * D_];
__device__ float g_scores[(size_t)B_ * NH_ * S_ * S_];
__device__ float g_mlp[(size_t)M_ * FF_];
__device__ float g_cls[B_ * D_];
__device__ float g_clsln[B_ * D_];

// ---------------- Helpers ----------------
__device__ __forceinline__ float gelu_exact(float x) {
    return 0.5f * x * (1.0f + erff(x * 0.70710678118654752440f));
}

__device__ __forceinline__ unsigned f2tf(float f) {
    unsigned u;
    asm("cvt.rna.tf32.f32 %0, %1;" : "=r"(u) : "f"(f));
    return u;
}

__device__ __forceinline__ float blockReduceSum256(float v) {
    __shared__ float sh[8];
    int lane = threadIdx.x & 31, wid = threadIdx.x >> 5;
#pragma unroll
    for (int o = 16; o > 0; o >>= 1) v += __shfl_down_sync(0xffffffffu, v, o);
    if (lane == 0) sh[wid] = v;
    __syncthreads();
    if (wid == 0) {
        v = (lane < 8) ? sh[lane] : 0.0f;
#pragma unroll
        for (int o = 4; o > 0; o >>= 1) v += __shfl_down_sync(0xffffffffu, v, o);
        if (lane == 0) sh[0] = v;
    }
    __syncthreads();
    float r = sh[0];
    __syncthreads();
    return r;
}

__device__ __forceinline__ float blockReduceMax256(float v) {
    __shared__ float sh[8];
    int lane = threadIdx.x & 31, wid = threadIdx.x >> 5;
#pragma unroll
    for (int o = 16; o > 0; o >>= 1) v = fmaxf(v, __shfl_down_sync(0xffffffffu, v, o));
    if (lane == 0) sh[wid] = v;
    __syncthreads();
    if (wid == 0) {
        v = (lane < 8) ? sh[lane] : -3.0e38f;
#pragma unroll
        for (int o = 4; o > 0; o >>= 1) v = fmaxf(v, __shfl_down_sync(0xffffffffu, v, o));
        if (lane == 0) sh[0] = v;
    }
    __syncthreads();
    float r = sh[0];
    __syncthreads();
    return r;
}

// ---------------- TF32 tensor-core GEMM ----------------
// C[M,N] = A[M,K] @ B[K,N] + bias (+gelu) (+res)
// 128x128x16 block tile, 8 warps (2x4), 64x32 warp tile, m16n8k8 TF32 mma.
// Requires K % 16 == 0, N % 4 == 0.
__global__ __launch_bounds__(256) void tf32gemm(
    const float* __restrict__ A, const float* __restrict__ Bm,
    const float* __restrict__ bias, const float* __restrict__ res,
    float* __restrict__ C, int M, int N, int K, int dogelu)
{
    __shared__ __align__(16) unsigned As[2][16][132];  // [k][m]
    __shared__ __align__(16) unsigned Bs[2][16][132];  // [k][n]

    const int tid = threadIdx.x;
    const int warp = tid >> 5, lane = tid & 31;
    const int wm = warp >> 2, wn = warp & 3;      // warp grid 2x4
    const int gid = lane >> 2, tig = lane & 3;
    const int m0 = blockIdx.y * 128, n0 = blockIdx.x * 128;

    float acc[4][4][4];
#pragma unroll
    for (int i = 0; i < 4; i++)
#pragma unroll
        for (int j = 0; j < 4; j++)
#pragma unroll
            for (int c = 0; c < 4; c++) acc[i][j][c] = 0.0f;

    unsigned ra[2][4], rb[2][4];

    auto ldg = [&](int k0) {
#pragma unroll
        for (int i = 0; i < 2; i++) {
            int lin = tid + i * 256;
            int row = lin >> 2, c4 = (lin & 3) * 4;      // A: 128 rows x 4 float4
            float4 av = make_float4(0.f, 0.f, 0.f, 0.f);
            if (m0 + row < M)
                av = *reinterpret_cast<const float4*>(A + (size_t)(m0 + row) * K + k0 + c4);
            ra[i][0] = f2tf(av.x); ra[i][1] = f2tf(av.y);
            ra[i][2] = f2tf(av.z); ra[i][3] = f2tf(av.w);

            int kr = lin >> 5, bc = (lin & 31) * 4;      // B: 16 rows x 32 float4
            int gn = n0 + bc;
            float4 bv = make_float4(0.f, 0.f, 0.f, 0.f);
            if (gn + 3 < N)
                bv = *reinterpret_cast<const float4*>(Bm + (size_t)(k0 + kr) * N + gn);
            rb[i][0] = f2tf(bv.x); rb[i][1] = f2tf(bv.y);
            rb[i][2] = f2tf(bv.z); rb[i][3] = f2tf(bv.w);
        }
    };

    auto sts = [&](int buf) {
#pragma unroll
        for (int i = 0; i < 2; i++) {
            int lin = tid + i * 256;
            int row = lin >> 2, c4 = (lin & 3) * 4;
#pragma unroll
            for (int j = 0; j < 4; j++) As[buf][c4 + j][row] = ra[i][j];
            int kr = lin >> 5, bc = (lin & 31) * 4;
            *reinterpret_cast<uint4*>(&Bs[buf][kr][bc]) =
                make_uint4(rb[i][0], rb[i][1], rb[i][2], rb[i][3]);
        }
    };

    const int nk = K >> 4;
    ldg(0);
    sts(0);
    __syncthreads();

    for (int ch = 0; ch < nk; ch++) {
        int cur = ch & 1;
        if (ch + 1 < nk) ldg((ch + 1) << 4);

#pragma unroll
        for (int kk = 0; kk < 2; kk++) {
            int k8 = kk * 8;
            unsigned af[4][4], bf[4][2];
#pragma unroll
            for (int mt = 0; mt < 4; mt++) {
                int mr = wm * 64 + mt * 16;
                af[mt][0] = As[cur][k8 + tig][mr + gid];
                af[mt][1] = As[cur][k8 + tig][mr + gid + 8];
                af[mt][2] = As[cur][k8 + tig + 4][mr + gid];
                af[mt][3] = As[cur][k8 + tig + 4][mr + gid + 8];
            }
#pragma unroll
            for (int nt = 0; nt < 4; nt++) {
                int nc = wn * 32 + nt * 8;
                bf[nt][0] = Bs[cur][k8 + tig][nc + gid];
                bf[nt][1] = Bs[cur][k8 + tig + 4][nc + gid];
            }
#pragma unroll
            for (int mt = 0; mt < 4; mt++)
#pragma unroll
                for (int nt = 0; nt < 4; nt++) {
                    asm volatile(
                        "mma.sync.aligned.m16n8k8.row.col.f32.tf32.tf32.f32 "
                        "{%0,%1,%2,%3}, {%4,%5,%6,%7}, {%8,%9}, {%0,%1,%2,%3};"
                        : "+f"(acc[mt][nt][0]), "+f"(acc[mt][nt][1]),
                          "+f"(acc[mt][nt][2]), "+f"(acc[mt][nt][3])
                        : "r"(af[mt][0]), "r"(af[mt][1]), "r"(af[mt][2]), "r"(af[mt][3]),
                          "r"(bf[nt][0]), "r"(bf[nt][1]));
                }
        }

        if (ch + 1 < nk) sts((ch + 1) & 1);
        __syncthreads();
    }

    // Epilogue
    auto emit = [&](int r, int c, float v0, float v1) {
        if (r >= M) return;
        if (c + 1 < N) {
            float2 o;
            o.x = v0 + bias[c];
            o.y = v1 + bias[c + 1];
            if (dogelu) { o.x = gelu_exact(o.x); o.y = gelu_exact(o.y); }
            if (res) {
                float2 rr = *reinterpret_cast<const float2*>(res + (size_t)r * N + c);
                o.x += rr.x; o.y += rr.y;
            }
            *reinterpret_cast<float2*>(C + (size_t)r * N + c) = o;
        } else if (c < N) {
            float v = v0 + bias[c];
            if (dogelu) v = gelu_exact(v);
            if (res) v += res[(size_t)r * N + c];
            C[(size_t)r * N + c] = v;
        }
    };

#pragma unroll
    for (int mt = 0; mt < 4; mt++) {
        int r0 = m0 + wm * 64 + mt * 16 + gid;
#pragma unroll
        for (int nt = 0; nt < 4; nt++) {
            int c0 = n0 + wn * 32 + nt * 8 + 2 * tig;
            emit(r0,     c0, acc[mt][nt][0], acc[mt][nt][1]);
            emit(r0 + 8, c0, acc[mt][nt][2], acc[mt][nt][3]);
        }
    }
}

// ---------------- LayerNorm ----------------
__global__ __launch_bounds__(256) void ln_kernel(
    const float* __restrict__ x, const float* __restrict__ w,
    const float* __restrict__ b, float* __restrict__ out)
{
    __shared__ float row[D_];
    int m = blockIdx.x;
    const float* xr = x + (size_t)m * D_;
    float s = 0.0f;
    for (int d = threadIdx.x; d < D_; d += 256) {
        float v = xr[d];
        row[d] = v;
        s += v;
    }
    __syncthreads();
    s = blockReduceSum256(s);
    float mean = s * (1.0f / D_);
    float s2 = 0.0f;
    for (int d = threadIdx.x; d < D_; d += 256) {
        float v = row[d] - mean;
        s2 += v * v;
    }
    s2 = blockReduceSum256(s2);
    float inv = 1.0f / (sqrtf(s2 * (1.0f / D_)) + EPS_);
    float* op = out + (size_t)m * D_;
    for (int d = threadIdx.x; d < D_; d += 256)
        op[d] = (row[d] - mean) * inv * w[d] + b[d];
}

// ---------------- Attention: scores = Q K^T / 8 ----------------
__global__ __launch_bounds__(256) void scores_kernel(
    const float* __restrict__ q, const float* __restrict__ k, float* __restrict__ s)
{
    __shared__ float Qs[16][68];
    __shared__ float Ks[16][68];
    int bh = blockIdx.z;
    int b = bh / NH_, h = bh % NH_;
    int i0 = blockIdx.y * 16, j0 = blockIdx.x * 16;
    int t = threadIdx.x;
    int r = t >> 4, c = (t & 15) * 4;

    float4 qv = make_float4(0.f, 0.f, 0.f, 0.f);
    if (i0 + r < S_)
        qv = *reinterpret_cast<const float4*>(q + (size_t)(b * S_ + i0 + r) * D_ + h * HD_ + c);
    *reinterpret_cast<float4*>(&Qs[r][c]) = qv;

    float4 kv = make_float4(0.f, 0.f, 0.f, 0.f);
    if (j0 + r < S_)
        kv = *reinterpret_cast<const float4*>(k + (size_t)(b * S_ + j0 + r) * D_ + h * HD_ + c);
    *reinterpret_cast<float4*>(&Ks[r][c]) = kv;

    __syncthreads();

    int ty = t >> 4, tx = t & 15;
    float acc = 0.0f;
#pragma unroll
    for (int cc = 0; cc < HD_; cc++) acc = fmaf(Qs[ty][cc], Ks[tx][cc], acc);

    int i = i0 + ty, j = j0 + tx;
    if (i < S_ && j < S_)
        s[((size_t)bh * S_ + i) * S_ + j] = acc * 0.125f;
}

// ---------------- Softmax over last dim (len 197) ----------------
__global__ __launch_bounds__(256) void softmax_kernel(float* __restrict__ s)
{
    int r = blockIdx.x;
    float* p = s + (size_t)r * S_;
    int t = threadIdx.x;
    float v = (t < S_) ? p[t] : -3.0e38f;
    float mx = blockReduceMax256(v);
    float e = (t < S_) ? expf(v - mx) : 0.0f;
    float sum = blockReduceSum256(e);
    if (t < S_) p[t] = e / sum;
}

// ---------------- y = attn @ V (merge heads into [B*S, D]) ----------------
__global__ __launch_bounds__(256) void av_kernel(
    const float* __restrict__ att, const float* __restrict__ v, float* __restrict__ y)
{
    __shared__ float As[16][17];
    __shared__ float Vs[16][68];
    int bh = blockIdx.y;
    int b = bh / NH_, h = bh % NH_;
    int i0 = blockIdx.x * 16;
    int t = threadIdx.x;
    int tx = t & 15, ty = t >> 4;

    float a0 = 0.f, a1 = 0.f, a2 = 0.f, a3 = 0.f;
    for (int j0 = 0; j0 < S_; j0 += 16) {
        int i = i0 + ty, j = j0 + tx;
        As[ty][tx] = (i < S_ && j < S_) ? att[((size_t)bh * S_ + i) * S_ + j] : 0.0f;

        int r = t >> 4, c = (t & 15) * 4;
        float4 vv = make_float4(0.f, 0.f, 0.f, 0.f);
        if (j0 + r < S_)
            vv = *reinterpret_cast<const float4*>(v + (size_t)(b * S_ + j0 + r) * D_ + h * HD_ + c);
        *reinterpret_cast<float4*>(&Vs[r][c]) = vv;

        __syncthreads();
#pragma unroll
        for (int jj = 0; jj < 16; jj++) {
            float a = As[ty][jj];
            a0 = fmaf(a, Vs[jj][tx], a0);
            a1 = fmaf(a, Vs[jj][tx + 16], a1);
            a2 = fmaf(a, Vs[jj][tx + 32], a2);
            a3 = fmaf(a, Vs[jj][tx + 48], a3);
        }
        __syncthreads();
    }
    int i = i0 + ty;
    if (i < S_) {
        float* yp = y + (size_t)(b * S_ + i) * D_ + h * HD_;
        yp[tx] = a0;
        yp[tx + 16] = a1;
        yp[tx + 32] = a2;
        yp[tx + 48] = a3;
    }
}

// ---------------- Patch gather ----------------
__global__ void patch_gather(const float* __restrict__ x)
{
    int idx = blockIdx.x * blockDim.x + threadIdx.x;
    if (idx >= MP_ * D_) return;
    int r = idx / D_, kk = idx - r * D_;
    int b = r / NP_, p = r - b * NP_;
    int ph = p / 14, pw = p - ph * 14;
    int c = kk >> 8;
    int rem = kk & 255;
    int pi = rem >> 4, pj = rem & 15;
    g_patches[idx] = x[((size_t)(b * 3 + c) * 224 + ph * 16 + pi) * 224 + pw * 16 + pj];
}

// ---------------- Assemble h ----------------
__global__ void assemble(const float* __restrict__ cls_token, const float* __restrict__ pos)
{
    int idx = blockIdx.x * blockDim.x + threadIdx.x;
    if (idx >= M_ * D_) return;
    int m = idx / D_, d = idx - m * D_;
    int b = m / S_, s = m - b * S_;
    float val;
    if (s == 0)
        val = cls_token[d] + pos[d];
    else
        val = g_hp[((size_t)b * NP_ + (s - 1)) * D_ + d] + pos[(size_t)s * D_ + d];
    g_h[idx] = val;
}

// ---------------- Extract CLS rows ----------------
__global__ void cls_extract()
{
    int idx = blockIdx.x * blockDim.x + threadIdx.x;
    if (idx >= B_ * D_) return;
    int b = idx / D_, d = idx - b * D_;
    g_cls[idx] = g_h[((size_t)b * S_) * D_ + d];
}

// ---------------- Host orchestration ----------------
extern "C" void kernel_launch(void* const* d_in, const int* in_sizes, int n_in,
                              void* d_out, int out_size)
{
    (void)in_sizes; (void)n_in; (void)out_size;
    const float* x         = (const float*)d_in[0];
    const float* patch_w   = (const float*)d_in[1];
    const float* patch_b   = (const float*)d_in[2];
    const float* cls_token = (const float*)d_in[3];
    const float* pos_emb   = (const float*)d_in[4];
    const float* ln1_w     = (const float*)d_in[5];
    const float* ln1_b     = (const float*)d_in[6];
    const float* wq        = (const float*)d_in[7];
    const float* bq        = (const float*)d_in[8];
    const float* wk        = (const float*)d_in[9];
    const float* bk        = (const float*)d_in[10];
    const float* wv        = (const float*)d_in[11];
    const float* bv        = (const float*)d_in[12];
    const float* wy        = (const float*)d_in[13];
    const float* by        = (const float*)d_in[14];
    const float* ln2_w     = (const float*)d_in[15];
    const float* ln2_b     = (const float*)d_in[16];
    const float* m1w       = (const float*)d_in[17];
    const float* m1b       = (const float*)d_in[18];
    const float* m2w       = (const float*)d_in[19];
    const float* m2b       = (const float*)d_in[20];
    const float* hlnw      = (const float*)d_in[21];
    const float* hlnb      = (const float*)d_in[22];
    const float* hw        = (const float*)d_in[23];
    const float* hb        = (const float*)d_in[24];
    float* out = (float*)d_out;

    float *patches, *hp, *h, *z, *q, *k, *v, *y, *sc, *mlp, *cls, *clsln;
    cudaGetSymbolAddress((void**)&patches, g_patches);
    cudaGetSymbolAddress((void**)&hp, g_hp);
    cudaGetSymbolAddress((void**)&h, g_h);
    cudaGetSymbolAddress((void**)&z, g_z);
    cudaGetSymbolAddress((void**)&q, g_q);
    cudaGetSymbolAddress((void**)&k, g_k);
    cudaGetSymbolAddress((void**)&v, g_v);
    cudaGetSymbolAddress((void**)&y, g_y);
    cudaGetSymbolAddress((void**)&sc, g_scores);
    cudaGetSymbolAddress((void**)&mlp, g_mlp);
    cudaGetSymbolAddress((void**)&cls, g_cls);
    cudaGetSymbolAddress((void**)&clsln, g_clsln);

    auto gemm = [&](const float* A, const float* Bm, const float* bias, const float* res,
                    float* C, int M, int N, int K, int dogelu) {
        dim3 g((N + 127) / 128, (M + 127) / 128);
        tf32gemm<<<g, 256>>>(A, Bm, bias, res, C, M, N, K, dogelu);
    };

    // Patch embedding
    patch_gather<<<(MP_ * D_ + 255) / 256, 256>>>(x);
    gemm(patches, patch_w, patch_b, nullptr, hp, MP_, D_, D_, 0);
    assemble<<<(M_ * D_ + 255) / 256, 256>>>(cls_token, pos_emb);

    // Transformer blocks
    for (int l = 0; l < L_; l++) {
        const size_t wo = (size_t)l * D_ * D_;
        const size_t bo = (size_t)l * D_;

        ln_kernel<<<M_, 256>>>(h, ln1_w + bo, ln1_b + bo, z);
        gemm(z, wq + wo, bq + bo, nullptr, q, M_, D_, D_, 0);
        gemm(z, wk + wo, bk + bo, nullptr, k, M_, D_, D_, 0);
        gemm(z, wv + wo, bv + bo, nullptr, v, M_, D_, D_, 0);

        dim3 gs((S_ + 15) / 16, (S_ + 15) / 16, B_ * NH_);
        scores_kernel<<<gs, 256>>>(q, k, sc);
        softmax_kernel<<<B_ * NH_ * S_, 256>>>(sc);
        dim3 ga((S_ + 15) / 16, B_ * NH_);
        av_kernel<<<ga, 256>>>(sc, v, y);

        gemm(y, wy + wo, by + bo, h, h, M_, D_, D_, 0);  // residual 1 (in-place)

        ln_kernel<<<M_, 256>>>(h, ln2_w + bo, ln2_b + bo, z);
        gemm(z, m1w + (size_t)l * D_ * FF_, m1b + (size_t)l * FF_, nullptr, mlp, M_, FF_, D_, 1);
        gemm(mlp, m2w + (size_t)l * FF_ * D_, m2b + bo, h, h, M_, D_, FF_, 0);  // residual 2
    }

    // Head
    cls_extract<<<(B_ * D_ + 255) / 256, 256>>>();
    ln_kernel<<<B_, 256>>>(cls, hlnw, hlnb, clsln);
    gemm(clsln, hw, hb, nullptr, out, B_, NC_, D_, 0);
}

// round 3
// speedup vs baseline: 2.5580x; 1.1446x over previous
#include <cuda_runtime.h>
#include <math.h>

// ---------------- Problem constants ----------------
#define B_   32
#define S_   197
#define NP_  196
#define D_   768
#define FF_  3072
#define L_   12
#define NH_  12
#define HD_  64
#define NC_  1000
#define M_   (B_ * S_)    // 6304
#define MP_  (B_ * NP_)   // 6272
#define EPS_ 1e-5f

// ---------------- Scratch (device globals; no allocs allowed) ----------------
__device__ float g_patches[(size_t)MP_ * D_];
__device__ float g_hp[(size_t)MP_ * D_];
__device__ float g_h[(size_t)M_ * D_];
__device__ float g_z[(size_t)M_ * D_];
__device__ float g_q[(size_t)M_ * D_];
__device__ float g_k[(size_t)M_ * D_];
__device__ float g_v[(size_t)M_ * D_];
__device__ float g_y[(size_t)M_ * D_];
__device__ float g_mlp[(size_t)M_ * FF_];
__device__ float g_cls[B_ * D_];
__device__ float g_clsln[B_ * D_];

// ---------------- Helpers ----------------
__device__ __forceinline__ float gelu_exact(float x) {
    return 0.5f * x * (1.0f + erff(x * 0.70710678118654752440f));
}

__device__ __forceinline__ unsigned f2tf(float f) {
    unsigned u;
    asm("cvt.rna.tf32.f32 %0, %1;" : "=r"(u) : "f"(f));
    return u;
}

__device__ __forceinline__ float blockReduceSum256(float v) {
    __shared__ float sh[8];
    int lane = threadIdx.x & 31, wid = threadIdx.x >> 5;
#pragma unroll
    for (int o = 16; o > 0; o >>= 1) v += __shfl_down_sync(0xffffffffu, v, o);
    if (lane == 0) sh[wid] = v;
    __syncthreads();
    if (wid == 0) {
        v = (lane < 8) ? sh[lane] : 0.0f;
#pragma unroll
        for (int o = 4; o > 0; o >>= 1) v += __shfl_down_sync(0xffffffffu, v, o);
        if (lane == 0) sh[0] = v;
    }
    __syncthreads();
    float r = sh[0];
    __syncthreads();
    return r;
}

// ---------------- TF32 tensor-core GEMM ----------------
__global__ __launch_bounds__(256) void tf32gemm(
    const float* __restrict__ A, const float* __restrict__ Bm,
    const float* __restrict__ bias, const float* __restrict__ res,
    float* __restrict__ C, int M, int N, int K, int dogelu)
{
    __shared__ __align__(16) unsigned As[2][16][132];  // [k][m]
    __shared__ __align__(16) unsigned Bs[2][16][132];  // [k][n]

    const int tid = threadIdx.x;
    const int warp = tid >> 5, lane = tid & 31;
    const int wm = warp >> 2, wn = warp & 3;      // warp grid 2x4
    const int gid = lane >> 2, tig = lane & 3;
    const int m0 = blockIdx.y * 128, n0 = blockIdx.x * 128;

    float acc[4][4][4];
#pragma unroll
    for (int i = 0; i < 4; i++)
#pragma unroll
        for (int j = 0; j < 4; j++)
#pragma unroll
            for (int c = 0; c < 4; c++) acc[i][j][c] = 0.0f;

    unsigned ra[2][4], rb[2][4];

    auto ldg = [&](int k0) {
#pragma unroll
        for (int i = 0; i < 2; i++) {
            int lin = tid + i * 256;
            int row = lin >> 2, c4 = (lin & 3) * 4;
            float4 av = make_float4(0.f, 0.f, 0.f, 0.f);
            if (m0 + row < M)
                av = *reinterpret_cast<const float4*>(A + (size_t)(m0 + row) * K + k0 + c4);
            ra[i][0] = f2tf(av.x); ra[i][1] = f2tf(av.y);
            ra[i][2] = f2tf(av.z); ra[i][3] = f2tf(av.w);

            int kr = lin >> 5, bc = (lin & 31) * 4;
            int gn = n0 + bc;
            float4 bv = make_float4(0.f, 0.f, 0.f, 0.f);
            if (gn + 3 < N)
                bv = *reinterpret_cast<const float4*>(Bm + (size_t)(k0 + kr) * N + gn);
            rb[i][0] = f2tf(bv.x); rb[i][1] = f2tf(bv.y);
            rb[i][2] = f2tf(bv.z); rb[i][3] = f2tf(bv.w);
        }
    };

    auto sts = [&](int buf) {
#pragma unroll
        for (int i = 0; i < 2; i++) {
            int lin = tid + i * 256;
            int row = lin >> 2, c4 = (lin & 3) * 4;
#pragma unroll
            for (int j = 0; j < 4; j++) As[buf][c4 + j][row] = ra[i][j];
            int kr = lin >> 5, bc = (lin & 31) * 4;
            *reinterpret_cast<uint4*>(&Bs[buf][kr][bc]) =
                make_uint4(rb[i][0], rb[i][1], rb[i][2], rb[i][3]);
        }
    };

    const int nk = K >> 4;
    ldg(0);
    sts(0);
    __syncthreads();

    for (int ch = 0; ch < nk; ch++) {
        int cur = ch & 1;
        if (ch + 1 < nk) ldg((ch + 1) << 4);

#pragma unroll
        for (int kk = 0; kk < 2; kk++) {
            int k8 = kk * 8;
            unsigned af[4][4], bf[4][2];
#pragma unroll
            for (int mt = 0; mt < 4; mt++) {
                int mr = wm * 64 + mt * 16;
                af[mt][0] = As[cur][k8 + tig][mr + gid];
                af[mt][1] = As[cur][k8 + tig][mr + gid + 8];
                af[mt][2] = As[cur][k8 + tig + 4][mr + gid];
                af[mt][3] = As[cur][k8 + tig + 4][mr + gid + 8];
            }
#pragma unroll
            for (int nt = 0; nt < 4; nt++) {
                int nc = wn * 32 + nt * 8;
                bf[nt][0] = Bs[cur][k8 + tig][nc + gid];
                bf[nt][1] = Bs[cur][k8 + tig + 4][nc + gid];
            }
#pragma unroll
            for (int mt = 0; mt < 4; mt++)
#pragma unroll
                for (int nt = 0; nt < 4; nt++) {
                    asm volatile(
                        "mma.sync.aligned.m16n8k8.row.col.f32.tf32.tf32.f32 "
                        "{%0,%1,%2,%3}, {%4,%5,%6,%7}, {%8,%9}, {%0,%1,%2,%3};"
                        : "+f"(acc[mt][nt][0]), "+f"(acc[mt][nt][1]),
                          "+f"(acc[mt][nt][2]), "+f"(acc[mt][nt][3])
                        : "r"(af[mt][0]), "r"(af[mt][1]), "r"(af[mt][2]), "r"(af[mt][3]),
                          "r"(bf[nt][0]), "r"(bf[nt][1]));
                }
        }

        if (ch + 1 < nk) sts((ch + 1) & 1);
        __syncthreads();
    }

    auto emit = [&](int r, int c, float v0, float v1) {
        if (r >= M) return;
        if (c + 1 < N) {
            float2 o;
            o.x = v0 + bias[c];
            o.y = v1 + bias[c + 1];
            if (dogelu) { o.x = gelu_exact(o.x); o.y = gelu_exact(o.y); }
            if (res) {
                float2 rr = *reinterpret_cast<const float2*>(res + (size_t)r * N + c);
                o.x += rr.x; o.y += rr.y;
            }
            *reinterpret_cast<float2*>(C + (size_t)r * N + c) = o;
        } else if (c < N) {
            float v = v0 + bias[c];
            if (dogelu) v = gelu_exact(v);
            if (res) v += res[(size_t)r * N + c];
            C[(size_t)r * N + c] = v;
        }
    };

#pragma unroll
    for (int mt = 0; mt < 4; mt++) {
        int r0 = m0 + wm * 64 + mt * 16 + gid;
#pragma unroll
        for (int nt = 0; nt < 4; nt++) {
            int c0 = n0 + wn * 32 + nt * 8 + 2 * tig;
            emit(r0,     c0, acc[mt][nt][0], acc[mt][nt][1]);
            emit(r0 + 8, c0, acc[mt][nt][2], acc[mt][nt][3]);
        }
    }
}

// ---------------- Fused attention (exact fp32) ----------------
// grid = (4 q-tiles, B*NH). block = 256. Dynamic smem layout (floats):
//   QsT [64][68]  (d-major, transposed)        @ 0
//   KVs [64][68]  (K transposed / V row-major) @ 4352
//   Sb  [64][201] (score strip, stride 201)    @ 8704
//   rowl[64]                                   @ 21568
#define ATTN_SMEM_FLOATS (64 * 68 * 2 + 64 * 201 + 64)
#define ATTN_SMEM_BYTES  (ATTN_SMEM_FLOATS * 4)

__global__ __launch_bounds__(256) void attn_fused(
    const float* __restrict__ q, const float* __restrict__ k,
    const float* __restrict__ v, float* __restrict__ y)
{
    extern __shared__ float sm[];
    float* QsT = sm;                 // [64][68] indexed [d][row]
    float* KVs = sm + 4352;          // [64][68]
    float* Sb  = sm + 8704;          // [64][201]
    float* rowl = sm + 8704 + 64 * 201;

    const int tid = threadIdx.x;
    const int ty = tid >> 4, tx = tid & 15;
    const int bh = blockIdx.y;
    const int b = bh / NH_, h = bh % NH_;
    const int q0 = blockIdx.x * 64;

    // ---- load Q tile transposed: QsT[d][row] ----
#pragma unroll
    for (int i = 0; i < 4; i++) {
        int lin = tid + i * 256;
        int row = lin >> 4, c4 = (lin & 15) * 4;
        float4 val = make_float4(0.f, 0.f, 0.f, 0.f);
        int gr = q0 + row;
        if (gr < S_)
            val = *reinterpret_cast<const float4*>(q + (size_t)(b * S_ + gr) * D_ + h * HD_ + c4);
        QsT[(c4 + 0) * 68 + row] = val.x;
        QsT[(c4 + 1) * 68 + row] = val.y;
        QsT[(c4 + 2) * 68 + row] = val.z;
        QsT[(c4 + 3) * 68 + row] = val.w;
    }
    __syncthreads();

    // ---- phase 1: S = Q K^T / 8 into Sb ----
    for (int j0 = 0; j0 < S_; j0 += 64) {
#pragma unroll
        for (int i = 0; i < 4; i++) {
            int lin = tid + i * 256;
            int row = lin >> 4, c4 = (lin & 15) * 4;
            float4 val = make_float4(0.f, 0.f, 0.f, 0.f);
            int gr = j0 + row;
            if (gr < S_)
                val = *reinterpret_cast<const float4*>(k + (size_t)(b * S_ + gr) * D_ + h * HD_ + c4);
            KVs[(c4 + 0) * 68 + row] = val.x;
            KVs[(c4 + 1) * 68 + row] = val.y;
            KVs[(c4 + 2) * 68 + row] = val.z;
            KVs[(c4 + 3) * 68 + row] = val.w;
        }
        __syncthreads();

        float acc[4][4];
#pragma unroll
        for (int i = 0; i < 4; i++)
#pragma unroll
            for (int j = 0; j < 4; j++) acc[i][j] = 0.0f;

#pragma unroll 8
        for (int d = 0; d < HD_; d++) {
            float4 a = *reinterpret_cast<const float4*>(&QsT[d * 68 + ty * 4]);
            float4 bb = *reinterpret_cast<const float4*>(&KVs[d * 68 + tx * 4]);
            float av[4] = {a.x, a.y, a.z, a.w};
            float bv[4] = {bb.x, bb.y, bb.z, bb.w};
#pragma unroll
            for (int i = 0; i < 4; i++)
#pragma unroll
                for (int j = 0; j < 4; j++) acc[i][j] = fmaf(av[i], bv[j], acc[i][j]);
        }

#pragma unroll
        for (int i = 0; i < 4; i++)
#pragma unroll
            for (int j = 0; j < 4; j++) {
                int col = j0 + tx * 4 + j;
                if (col < S_) Sb[(ty * 4 + i) * 201 + col] = acc[i][j] * 0.125f;
            }
        __syncthreads();
    }

    // ---- phase 2: softmax rows (4 threads per row) ----
    {
        int row = tid >> 2, seg = tid & 3;
        float* sr = Sb + row * 201;
        float m = -3.0e38f;
        for (int c = seg; c < S_; c += 4) m = fmaxf(m, sr[c]);
        m = fmaxf(m, __shfl_xor_sync(0xffffffffu, m, 1));
        m = fmaxf(m, __shfl_xor_sync(0xffffffffu, m, 2));
        float l = 0.0f;
        for (int c = seg; c < S_; c += 4) {
            float e = expf(sr[c] - m);
            sr[c] = e;
            l += e;
        }
        l += __shfl_xor_sync(0xffffffffu, l, 1);
        l += __shfl_xor_sync(0xffffffffu, l, 2);
        if (seg == 0) rowl[row] = l;
    }
    __syncthreads();

    // ---- phase 3: O = P V ----
    float o[4][4];
#pragma unroll
    for (int i = 0; i < 4; i++)
#pragma unroll
        for (int j = 0; j < 4; j++) o[i][j] = 0.0f;

    for (int j0 = 0; j0 < S_; j0 += 64) {
#pragma unroll
        for (int i = 0; i < 4; i++) {
            int lin = tid + i * 256;
            int row = lin >> 4, c4 = (lin & 15) * 4;
            float4 val = make_float4(0.f, 0.f, 0.f, 0.f);
            int gr = j0 + row;
            if (gr < S_)
                val = *reinterpret_cast<const float4*>(v + (size_t)(b * S_ + gr) * D_ + h * HD_ + c4);
            *reinterpret_cast<float4*>(&KVs[row * 68 + c4]) = val;  // V row-major
        }
        __syncthreads();

        int jmax = (S_ - j0 < 64) ? (S_ - j0) : 64;
#pragma unroll 8
        for (int jj = 0; jj < jmax; jj++) {
            float4 bb = *reinterpret_cast<const float4*>(&KVs[jj * 68 + tx * 4]);
            float bv[4] = {bb.x, bb.y, bb.z, bb.w};
            float av[4];
#pragma unroll
            for (int i = 0; i < 4; i++) av[i] = Sb[(ty * 4 + i) * 201 + j0 + jj];
#pragma unroll
            for (int i = 0; i < 4; i++)
#pragma unroll
                for (int j = 0; j < 4; j++) o[i][j] = fmaf(av[i], bv[j], o[i][j]);
        }
        __syncthreads();
    }

    // ---- write out (merge heads) ----
#pragma unroll
    for (int i = 0; i < 4; i++) {
        int gr = q0 + ty * 4 + i;
        if (gr < S_) {
            float linv = 1.0f / rowl[ty * 4 + i];
            float4 ov = make_float4(o[i][0] * linv, o[i][1] * linv,
                                    o[i][2] * linv, o[i][3] * linv);
            *reinterpret_cast<float4*>(y + (size_t)(b * S_ + gr) * D_ + h * HD_ + tx * 4) = ov;
        }
    }
}

// ---------------- LayerNorm ----------------
__global__ __launch_bounds__(256) void ln_kernel(
    const float* __restrict__ x, const float* __restrict__ w,
    const float* __restrict__ b, float* __restrict__ out)
{
    __shared__ float row[D_];
    int m = blockIdx.x;
    const float* xr = x + (size_t)m * D_;
    float s = 0.0f;
    for (int d = threadIdx.x; d < D_; d += 256) {
        float v = xr[d];
        row[d] = v;
        s += v;
    }
    __syncthreads();
    s = blockReduceSum256(s);
    float mean = s * (1.0f / D_);
    float s2 = 0.0f;
    for (int d = threadIdx.x; d < D_; d += 256) {
        float v = row[d] - mean;
        s2 += v * v;
    }
    s2 = blockReduceSum256(s2);
    float inv = 1.0f / (sqrtf(s2 * (1.0f / D_)) + EPS_);
    float* op = out + (size_t)m * D_;
    for (int d = threadIdx.x; d < D_; d += 256)
        op[d] = (row[d] - mean) * inv * w[d] + b[d];
}

// ---------------- Patch gather ----------------
__global__ void patch_gather(const float* __restrict__ x)
{
    int idx = blockIdx.x * blockDim.x + threadIdx.x;
    if (idx >= MP_ * D_) return;
    int r = idx / D_, kk = idx - r * D_;
    int b = r / NP_, p = r - b * NP_;
    int ph = p / 14, pw = p - ph * 14;
    int c = kk >> 8;
    int rem = kk & 255;
    int pi = rem >> 4, pj = rem & 15;
    g_patches[idx] = x[((size_t)(b * 3 + c) * 224 + ph * 16 + pi) * 224 + pw * 16 + pj];
}

// ---------------- Assemble h ----------------
__global__ void assemble(const float* __restrict__ cls_token, const float* __restrict__ pos)
{
    int idx = blockIdx.x * blockDim.x + threadIdx.x;
    if (idx >= M_ * D_) return;
    int m = idx / D_, d = idx - m * D_;
    int b = m / S_, s = m - b * S_;
    float val;
    if (s == 0)
        val = cls_token[d] + pos[d];
    else
        val = g_hp[((size_t)b * NP_ + (s - 1)) * D_ + d] + pos[(size_t)s * D_ + d];
    g_h[idx] = val;
}

// ---------------- Extract CLS rows ----------------
__global__ void cls_extract()
{
    int idx = blockIdx.x * blockDim.x + threadIdx.x;
    if (idx >= B_ * D_) return;
    int b = idx / D_, d = idx - b * D_;
    g_cls[idx] = g_h[((size_t)b * S_) * D_ + d];
}

// ---------------- Host orchestration ----------------
extern "C" void kernel_launch(void* const* d_in, const int* in_sizes, int n_in,
                              void* d_out, int out_size)
{
    (void)in_sizes; (void)n_in; (void)out_size;
    const float* x         = (const float*)d_in[0];
    const float* patch_w   = (const float*)d_in[1];
    const float* patch_b   = (const float*)d_in[2];
    const float* cls_token = (const float*)d_in[3];
    const float* pos_emb   = (const float*)d_in[4];
    const float* ln1_w     = (const float*)d_in[5];
    const float* ln1_b     = (const float*)d_in[6];
    const float* wq        = (const float*)d_in[7];
    const float* bq        = (const float*)d_in[8];
    const float* wk        = (const float*)d_in[9];
    const float* bk        = (const float*)d_in[10];
    const float* wv        = (const float*)d_in[11];
    const float* bv        = (const float*)d_in[12];
    const float* wy        = (const float*)d_in[13];
    const float* by        = (const float*)d_in[14];
    const float* ln2_w     = (const float*)d_in[15];
    const float* ln2_b     = (const float*)d_in[16];
    const float* m1w       = (const float*)d_in[17];
    const float* m1b       = (const float*)d_in[18];
    const float* m2w       = (const float*)d_in[19];
    const float* m2b       = (const float*)d_in[20];
    const float* hlnw      = (const float*)d_in[21];
    const float* hlnb      = (const float*)d_in[22];
    const float* hw        = (const float*)d_in[23];
    const float* hb        = (const float*)d_in[24];
    float* out = (float*)d_out;

    float *patches, *hp, *h, *z, *q, *k, *v, *y, *mlp, *cls, *clsln;
    cudaGetSymbolAddress((void**)&patches, g_patches);
    cudaGetSymbolAddress((void**)&hp, g_hp);
    cudaGetSymbolAddress((void**)&h, g_h);
    cudaGetSymbolAddress((void**)&z, g_z);
    cudaGetSymbolAddress((void**)&q, g_q);
    cudaGetSymbolAddress((void**)&k, g_k);
    cudaGetSymbolAddress((void**)&v, g_v);
    cudaGetSymbolAddress((void**)&y, g_y);
    cudaGetSymbolAddress((void**)&mlp, g_mlp);
    cudaGetSymbolAddress((void**)&cls, g_cls);
    cudaGetSymbolAddress((void**)&clsln, g_clsln);

    cudaFuncSetAttribute(attn_fused, cudaFuncAttributeMaxDynamicSharedMemorySize,
                         ATTN_SMEM_BYTES);

    auto gemm = [&](const float* A, const float* Bm, const float* bias, const float* res,
                    float* C, int M, int N, int K, int dogelu) {
        dim3 g((N + 127) / 128, (M + 127) / 128);
        tf32gemm<<<g, 256>>>(A, Bm, bias, res, C, M, N, K, dogelu);
    };

    // Patch embedding
    patch_gather<<<(MP_ * D_ + 255) / 256, 256>>>(x);
    gemm(patches, patch_w, patch_b, nullptr, hp, MP_, D_, D_, 0);
    assemble<<<(M_ * D_ + 255) / 256, 256>>>(cls_token, pos_emb);

    // Transformer blocks
    for (int l = 0; l < L_; l++) {
        const size_t wo = (size_t)l * D_ * D_;
        const size_t bo = (size_t)l * D_;

        ln_kernel<<<M_, 256>>>(h, ln1_w + bo, ln1_b + bo, z);
        gemm(z, wq + wo, bq + bo, nullptr, q, M_, D_, D_, 0);
        gemm(z, wk + wo, bk + bo, nullptr, k, M_, D_, D_, 0);
        gemm(z, wv + wo, bv + bo, nullptr, v, M_, D_, D_, 0);

        attn_fused<<<dim3(4, B_ * NH_), 256, ATTN_SMEM_BYTES>>>(q, k, v, y);

        gemm(y, wy + wo, by + bo, h, h, M_, D_, D_, 0);  // residual 1

        ln_kernel<<<M_, 256>>>(h, ln2_w + bo, ln2_b + bo, z);
        gemm(z, m1w + (size_t)l * D_ * FF_, m1b + (size_t)l * FF_, nullptr, mlp, M_, FF_, D_, 1);
        gemm(mlp, m2w + (size_t)l * FF_ * D_, m2b + bo, h, h, M_, D_, FF_, 0);  // residual 2
    }

    // Head
    cls_extract<<<(B_ * D_ + 255) / 256, 256>>>();
    ln_kernel<<<B_, 256>>>(cls, hlnw, hlnb, clsln);
    gemm(clsln, hw, hb, nullptr, out, B_, NC_, D_, 0);
}

// round 7
// speedup vs baseline: 3.4646x; 1.3544x over previous
#include <cuda_runtime.h>
#include <stdint.h>
#include <math.h>

// ---------------- Problem constants ----------------
#define B_   32
#define S_   197
#define NP_  196
#define D_   768
#define FF_  3072
#define L_   12
#define NH_  12
#define HD_  64
#define NC_  1000
#define M_   (B_ * S_)    // 6304
#define MP_  (B_ * NP_)   // 6272
#define EPS_ 1e-5f

// ---------------- Scratch (device globals; no allocs allowed) ----------------
__device__ float g_patches[(size_t)MP_ * D_];
__device__ float g_hp[(size_t)MP_ * D_];
__device__ float g_h[(size_t)M_ * D_];
__device__ float g_z[(size_t)M_ * D_];
__device__ float g_q[(size_t)M_ * D_];
__device__ float g_k[(size_t)M_ * D_];
__device__ float g_v[(size_t)M_ * D_];
__device__ float g_y[(size_t)M_ * D_];
__device__ float g_mlp[(size_t)M_ * FF_];
__device__ float g_cls[B_ * D_];
__device__ float g_clsln[B_ * D_];

// ---------------- Helpers ----------------
__device__ __forceinline__ float gelu_exact(float x) {
    return 0.5f * x * (1.0f + erff(x * 0.70710678118654752440f));
}

__device__ __forceinline__ unsigned f2tf(float f) {
    unsigned u;
    asm("cvt.rna.tf32.f32 %0, %1;" : "=r"(u) : "f"(f));
    return u;
}

__device__ __forceinline__ float blockReduceSum256(float v) {
    __shared__ float sh[8];
    int lane = threadIdx.x & 31, wid = threadIdx.x >> 5;
#pragma unroll
    for (int o = 16; o > 0; o >>= 1) v += __shfl_down_sync(0xffffffffu, v, o);
    if (lane == 0) sh[wid] = v;
    __syncthreads();
    if (wid == 0) {
        v = (lane < 8) ? sh[lane] : 0.0f;
#pragma unroll
        for (int o = 4; o > 0; o >>= 1) v += __shfl_down_sync(0xffffffffu, v, o);
        if (lane == 0) sh[0] = v;
    }
    __syncthreads();
    float r = sh[0];
    __syncthreads();
    return r;
}

// ---------------- TF32 tensor-core GEMM, cp.async 4-stage pipeline ----------------
// C[M,N] = A[M,K] @ B[K,N] + bias (+gelu) (+res)
// 128x128x16 block tile, 8 warps (2x4), 64x32 warp tile, m16n8k8 TF32 mma.
// Requires K % 16 == 0, N % 4 == 0.
#define GSTAGES 4
#define APAD 20   // floats per A row (16 + 4), conflict-free
#define BPAD 136  // floats per B k-row (128 + 8), conflict-free
#define STAGE_FLOATS (128 * APAD + 16 * BPAD)  // 2560 + 2176 = 4736
#define GEMM_SMEM_BYTES (GSTAGES * STAGE_FLOATS * 4)  // 75776

__device__ __forceinline__ void cp16(uint32_t dst, const void* src, int pred16) {
    asm volatile("cp.async.ca.shared.global [%0], [%1], 16, %2;"
                 :: "r"(dst), "l"(src), "r"(pred16));
}

__global__ __launch_bounds__(256) void tf32gemm(
    const float* __restrict__ A, const float* __restrict__ Bm,
    const float* __restrict__ bias, const float* __restrict__ res,
    float* __restrict__ C, int M, int N, int K, int dogelu)
{
    extern __shared__ float smem[];

    const int tid = threadIdx.x;
    const int warp = tid >> 5, lane = tid & 31;
    const int wm = warp >> 2, wn = warp & 3;      // warp grid 2x4
    const int gid = lane >> 2, tig = lane & 3;
    const int m0 = blockIdx.y * 128, n0 = blockIdx.x * 128;

    // per-thread copy coordinates (2 float4 each for A and B per stage)
    // A tile: 128 rows x 16 k-floats = 512 float4; lin>>2 = row, (lin&3)*4 = k col
    const int ar0 = tid >> 2,             ac0 = (tid & 3) * 4;   // lin = tid      -> rows 0..63
    const int ar1 = (tid + 256) >> 2,     ac1 = ac0;             // lin = tid+256  -> rows 64..127
    const int bk0 = tid >> 5,             bc0 = (tid & 31) * 4;  // B rows 0..7
    const int bk1 = (tid + 256) >> 5,     bc1 = bc0;             // B rows 8..15

    uint32_t smem_u32 = (uint32_t)__cvta_generic_to_shared(smem);

    auto issue_stage = [&](int k0, int buf) {
        uint32_t sa = smem_u32 + (uint32_t)(buf * STAGE_FLOATS) * 4u;
        uint32_t sb = sa + 128u * APAD * 4u;
        // A: rows ar, k cols k0+ac .. +3
        {
            int p = (m0 + ar0 < M) ? 16 : 0;
            cp16(sa + (uint32_t)(ar0 * APAD + ac0) * 4u,
                 A + (size_t)(m0 + ar0) * K + k0 + ac0, p);
            int p1 = (m0 + ar1 < M) ? 16 : 0;
            cp16(sa + (uint32_t)(ar1 * APAD + ac1) * 4u,
                 A + (size_t)(m0 + ar1) * K + k0 + ac1, p1);
        }
        // B: k rows k0+bk, n cols n0+bc .. +3
        {
            int gn = n0 + bc0;
            int p = (gn + 3 < N) ? 16 : 0;
            cp16(sb + (uint32_t)(bk0 * BPAD + bc0) * 4u,
                 Bm + (size_t)(k0 + bk0) * N + gn, p);
            int p1 = (gn + 3 < N) ? 16 : 0;
            cp16(sb + (uint32_t)(bk1 * BPAD + bc1) * 4u,
                 Bm + (size_t)(k0 + bk1) * N + gn, p1);
        }
        asm volatile("cp.async.commit_group;");
    };

    float acc[4][4][4];
#pragma unroll
    for (int i = 0; i < 4; i++)
#pragma unroll
        for (int j = 0; j < 4; j++)
#pragma unroll
            for (int c = 0; c < 4; c++) acc[i][j][c] = 0.0f;

    const int nk = K >> 4;

    // prologue: issue first GSTAGES-1 stages
#pragma unroll
    for (int s = 0; s < GSTAGES - 1; s++) {
        if (s < nk) issue_stage(s << 4, s);
        else asm volatile("cp.async.commit_group;");
    }

    for (int ch = 0; ch < nk; ch++) {
        asm volatile("cp.async.wait_group %0;" :: "n"(GSTAGES - 2));
        __syncthreads();

        // prefetch stage ch+GSTAGES-1 (writes buffer consumed at ch-1)
        int pf = ch + GSTAGES - 1;
        if (pf < nk) issue_stage(pf << 4, pf & (GSTAGES - 1));
        else asm volatile("cp.async.commit_group;");

        const float* sa = smem + (ch & (GSTAGES - 1)) * STAGE_FLOATS;
        const float* sb = sa + 128 * APAD;

#pragma unroll
        for (int kk = 0; kk < 2; kk++) {
            int k8 = kk * 8;
            unsigned af[4][4], bf[4][2];
#pragma unroll
            for (int mt = 0; mt < 4; mt++) {
                int mr = wm * 64 + mt * 16;
                af[mt][0] = f2tf(sa[(mr + gid) * APAD + k8 + tig]);
                af[mt][1] = f2tf(sa[(mr + gid + 8) * APAD + k8 + tig]);
                af[mt][2] = f2tf(sa[(mr + gid) * APAD + k8 + tig + 4]);
                af[mt][3] = f2tf(sa[(mr + gid + 8) * APAD + k8 + tig + 4]);
            }
#pragma unroll
            for (int nt = 0; nt < 4; nt++) {
                int nc = wn * 32 + nt * 8;
                bf[nt][0] = f2tf(sb[(k8 + tig) * BPAD + nc + gid]);
                bf[nt][1] = f2tf(sb[(k8 + tig + 4) * BPAD + nc + gid]);
            }
#pragma unroll
            for (int mt = 0; mt < 4; mt++)
#pragma unroll
                for (int nt = 0; nt < 4; nt++) {
                    asm volatile(
                        "mma.sync.aligned.m16n8k8.row.col.f32.tf32.tf32.f32 "
                        "{%0,%1,%2,%3}, {%4,%5,%6,%7}, {%8,%9}, {%0,%1,%2,%3};"
                        : "+f"(acc[mt][nt][0]), "+f"(acc[mt][nt][1]),
                          "+f"(acc[mt][nt][2]), "+f"(acc[mt][nt][3])
                        : "r"(af[mt][0]), "r"(af[mt][1]), "r"(af[mt][2]), "r"(af[mt][3]),
                          "r"(bf[nt][0]), "r"(bf[nt][1]));
                }
        }
        __syncthreads();
    }

    // Epilogue
    auto emit = [&](int r, int c, float v0, float v1) {
        if (r >= M) return;
        if (c + 1 < N) {
            float2 o;
            o.x = v0 + bias[c];
            o.y = v1 + bias[c + 1];
            if (dogelu) { o.x = gelu_exact(o.x); o.y = gelu_exact(o.y); }
            if (res) {
                float2 rr = *reinterpret_cast<const float2*>(res + (size_t)r * N + c);
                o.x += rr.x; o.y += rr.y;
            }
            *reinterpret_cast<float2*>(C + (size_t)r * N + c) = o;
        } else if (c < N) {
            float v = v0 + bias[c];
            if (dogelu) v = gelu_exact(v);
            if (res) v += res[(size_t)r * N + c];
            C[(size_t)r * N + c] = v;
        }
    };

#pragma unroll
    for (int mt = 0; mt < 4; mt++) {
        int r0 = m0 + wm * 64 + mt * 16 + gid;
#pragma unroll
        for (int nt = 0; nt < 4; nt++) {
            int c0 = n0 + wn * 32 + nt * 8 + 2 * tig;
            emit(r0,     c0, acc[mt][nt][0], acc[mt][nt][1]);
            emit(r0 + 8, c0, acc[mt][nt][2], acc[mt][nt][3]);
        }
    }
}

// ---------------- Fused attention (exact fp32) ----------------
#define ATTN_SMEM_FLOATS (64 * 68 * 2 + 64 * 201 + 64)
#define ATTN_SMEM_BYTES  (ATTN_SMEM_FLOATS * 4)

__global__ __launch_bounds__(256) void attn_fused(
    const float* __restrict__ q, const float* __restrict__ k,
    const float* __restrict__ v, float* __restrict__ y)
{
    extern __shared__ float smattn[];
    float* QsT = smattn;                 // [64][68] indexed [d][row]
    float* KVs = smattn + 4352;          // [64][68]
    float* Sb  = smattn + 8704;          // [64][201]
    float* rowl = smattn + 8704 + 64 * 201;

    const int tid = threadIdx.x;
    const int ty = tid >> 4, tx = tid & 15;
    const int bh = blockIdx.y;
    const int b = bh / NH_, h = bh % NH_;
    const int q0 = blockIdx.x * 64;

#pragma unroll
    for (int i = 0; i < 4; i++) {
        int lin = tid + i * 256;
        int row = lin >> 4, c4 = (lin & 15) * 4;
        float4 val = make_float4(0.f, 0.f, 0.f, 0.f);
        int gr = q0 + row;
        if (gr < S_)
            val = *reinterpret_cast<const float4*>(q + (size_t)(b * S_ + gr) * D_ + h * HD_ + c4);
        QsT[(c4 + 0) * 68 + row] = val.x;
        QsT[(c4 + 1) * 68 + row] = val.y;
        QsT[(c4 + 2) * 68 + row] = val.z;
        QsT[(c4 + 3) * 68 + row] = val.w;
    }
    __syncthreads();

    for (int j0 = 0; j0 < S_; j0 += 64) {
#pragma unroll
        for (int i = 0; i < 4; i++) {
            int lin = tid + i * 256;
            int row = lin >> 4, c4 = (lin & 15) * 4;
            float4 val = make_float4(0.f, 0.f, 0.f, 0.f);
            int gr = j0 + row;
            if (gr < S_)
                val = *reinterpret_cast<const float4*>(k + (size_t)(b * S_ + gr) * D_ + h * HD_ + c4);
            KVs[(c4 + 0) * 68 + row] = val.x;
            KVs[(c4 + 1) * 68 + row] = val.y;
            KVs[(c4 + 2) * 68 + row] = val.z;
            KVs[(c4 + 3) * 68 + row] = val.w;
        }
        __syncthreads();

        float acc[4][4];
#pragma unroll
        for (int i = 0; i < 4; i++)
#pragma unroll
            for (int j = 0; j < 4; j++) acc[i][j] = 0.0f;

#pragma unroll 8
        for (int d = 0; d < HD_; d++) {
            float4 a = *reinterpret_cast<const float4*>(&QsT[d * 68 + ty * 4]);
            float4 bb = *reinterpret_cast<const float4*>(&KVs[d * 68 + tx * 4]);
            float av[4] = {a.x, a.y, a.z, a.w};
            float bv[4] = {bb.x, bb.y, bb.z, bb.w};
#pragma unroll
            for (int i = 0; i < 4; i++)
#pragma unroll
                for (int j = 0; j < 4; j++) acc[i][j] = fmaf(av[i], bv[j], acc[i][j]);
        }

#pragma unroll
        for (int i = 0; i < 4; i++)
#pragma unroll
            for (int j = 0; j < 4; j++) {
                int col = j0 + tx * 4 + j;
                if (col < S_) Sb[(ty * 4 + i) * 201 + col] = acc[i][j] * 0.125f;
            }
        __syncthreads();
    }

    {
        int row = tid >> 2, seg = tid & 3;
        float* sr = Sb + row * 201;
        float m = -3.0e38f;
        for (int c = seg; c < S_; c += 4) m = fmaxf(m, sr[c]);
        m = fmaxf(m, __shfl_xor_sync(0xffffffffu, m, 1));
        m = fmaxf(m, __shfl_xor_sync(0xffffffffu, m, 2));
        float l = 0.0f;
        for (int c = seg; c < S_; c += 4) {
            float e = expf(sr[c] - m);
            sr[c] = e;
            l += e;
        }
        l += __shfl_xor_sync(0xffffffffu, l, 1);
        l += __shfl_xor_sync(0xffffffffu, l, 2);
        if (seg == 0) rowl[row] = l;
    }
    __syncthreads();

    float o[4][4];
#pragma unroll
    for (int i = 0; i < 4; i++)
#pragma unroll
        for (int j = 0; j < 4; j++) o[i][j] = 0.0f;

    for (int j0 = 0; j0 < S_; j0 += 64) {
#pragma unroll
        for (int i = 0; i < 4; i++) {
            int lin = tid + i * 256;
            int row = lin >> 4, c4 = (lin & 15) * 4;
            float4 val = make_float4(0.f, 0.f, 0.f, 0.f);
            int gr = j0 + row;
            if (gr < S_)
                val = *reinterpret_cast<const float4*>(v + (size_t)(b * S_ + gr) * D_ + h * HD_ + c4);
            *reinterpret_cast<float4*>(&KVs[row * 68 + c4]) = val;
        }
        __syncthreads();

        int jmax = (S_ - j0 < 64) ? (S_ - j0) : 64;
#pragma unroll 8
        for (int jj = 0; jj < jmax; jj++) {
            float4 bb = *reinterpret_cast<const float4*>(&KVs[jj * 68 + tx * 4]);
            float bv[4] = {bb.x, bb.y, bb.z, bb.w};
            float av[4];
#pragma unroll
            for (int i = 0; i < 4; i++) av[i] = Sb[(ty * 4 + i) * 201 + j0 + jj];
#pragma unroll
            for (int i = 0; i < 4; i++)
#pragma unroll
                for (int j = 0; j < 4; j++) o[i][j] = fmaf(av[i], bv[j], o[i][j]);
        }
        __syncthreads();
    }

#pragma unroll
    for (int i = 0; i < 4; i++) {
        int gr = q0 + ty * 4 + i;
        if (gr < S_) {
            float linv = 1.0f / rowl[ty * 4 + i];
            float4 ov = make_float4(o[i][0] * linv, o[i][1] * linv,
                                    o[i][2] * linv, o[i][3] * linv);
            *reinterpret_cast<float4*>(y + (size_t)(b * S_ + gr) * D_ + h * HD_ + tx * 4) = ov;
        }
    }
}

// ---------------- LayerNorm ----------------
__global__ __launch_bounds__(256) void ln_kernel(
    const float* __restrict__ x, const float* __restrict__ w,
    const float* __restrict__ b, float* __restrict__ out)
{
    __shared__ float row[D_];
    int m = blockIdx.x;
    const float* xr = x + (size_t)m * D_;
    float s = 0.0f;
    for (int d = threadIdx.x; d < D_; d += 256) {
        float v = xr[d];
        row[d] = v;
        s += v;
    }
    __syncthreads();
    s = blockReduceSum256(s);
    float mean = s * (1.0f / D_);
    float s2 = 0.0f;
    for (int d = threadIdx.x; d < D_; d += 256) {
        float v = row[d] - mean;
        s2 += v * v;
    }
    s2 = blockReduceSum256(s2);
    float inv = 1.0f / (sqrtf(s2 * (1.0f / D_)) + EPS_);
    float* op = out + (size_t)m * D_;
    for (int d = threadIdx.x; d < D_; d += 256)
        op[d] = (row[d] - mean) * inv * w[d] + b[d];
}

// ---------------- Patch gather ----------------
__global__ void patch_gather(const float* __restrict__ x)
{
    int idx = blockIdx.x * blockDim.x + threadIdx.x;
    if (idx >= MP_ * D_) return;
    int r = idx / D_, kk = idx - r * D_;
    int b = r / NP_, p = r - b * NP_;
    int ph = p / 14, pw = p - ph * 14;
    int c = kk >> 8;
    int rem = kk & 255;
    int pi = rem >> 4, pj = rem & 15;
    g_patches[idx] = x[((size_t)(b * 3 + c) * 224 + ph * 16 + pi) * 224 + pw * 16 + pj];
}

// ---------------- Assemble h ----------------
__global__ void assemble(const float* __restrict__ cls_token, const float* __restrict__ pos)
{
    int idx = blockIdx.x * blockDim.x + threadIdx.x;
    if (idx >= M_ * D_) return;
    int m = idx / D_, d = idx - m * D_;
    int b = m / S_, s = m - b * S_;
    float val;
    if (s == 0)
        val = cls_token[d] + pos[d];
    else
        val = g_hp[((size_t)b * NP_ + (s - 1)) * D_ + d] + pos[(size_t)s * D_ + d];
    g_h[idx] = val;
}

// ---------------- Extract CLS rows ----------------
__global__ void cls_extract()
{
    int idx = blockIdx.x * blockDim.x + threadIdx.x;
    if (idx >= B_ * D_) return;
    int b = idx / D_, d = idx - b * D_;
    g_cls[idx] = g_h[((size_t)b * S_) * D_ + d];
}

// ---------------- Host orchestration ----------------
extern "C" void kernel_launch(void* const* d_in, const int* in_sizes, int n_in,
                              void* d_out, int out_size)
{
    (void)in_sizes; (void)n_in; (void)out_size;
    const float* x         = (const float*)d_in[0];
    const float* patch_w   = (const float*)d_in[1];
    const float* patch_b   = (const float*)d_in[2];
    const float* cls_token = (const float*)d_in[3];
    const float* pos_emb   = (const float*)d_in[4];
    const float* ln1_w     = (const float*)d_in[5];
    const float* ln1_b     = (const float*)d_in[6];
    const float* wq        = (const float*)d_in[7];
    const float* bq        = (const float*)d_in[8];
    const float* wk        = (const float*)d_in[9];
    const float* bk        = (const float*)d_in[10];
    const float* wv        = (const float*)d_in[11];
    const float* bv        = (const float*)d_in[12];
    const float* wy        = (const float*)d_in[13];
    const float* by        = (const float*)d_in[14];
    const float* ln2_w     = (const float*)d_in[15];
    const float* ln2_b     = (const float*)d_in[16];
    const float* m1w       = (const float*)d_in[17];
    const float* m1b       = (const float*)d_in[18];
    const float* m2w       = (const float*)d_in[19];
    const float* m2b       = (const float*)d_in[20];
    const float* hlnw      = (const float*)d_in[21];
    const float* hlnb      = (const float*)d_in[22];
    const float* hw        = (const float*)d_in[23];
    const float* hb        = (const float*)d_in[24];
    float* out = (float*)d_out;

    float *patches, *hp, *h, *z, *q, *k, *v, *y, *mlp, *cls, *clsln;
    cudaGetSymbolAddress((void**)&patches, g_patches);
    cudaGetSymbolAddress((void**)&hp, g_hp);
    cudaGetSymbolAddress((void**)&h, g_h);
    cudaGetSymbolAddress((void**)&z, g_z);
    cudaGetSymbolAddress((void**)&q, g_q);
    cudaGetSymbolAddress((void**)&k, g_k);
    cudaGetSymbolAddress((void**)&v, g_v);
    cudaGetSymbolAddress((void**)&y, g_y);
    cudaGetSymbolAddress((void**)&mlp, g_mlp);
    cudaGetSymbolAddress((void**)&cls, g_cls);
    cudaGetSymbolAddress((void**)&clsln, g_clsln);

    cudaFuncSetAttribute(attn_fused, cudaFuncAttributeMaxDynamicSharedMemorySize,
                         ATTN_SMEM_BYTES);
    cudaFuncSetAttribute(tf32gemm, cudaFuncAttributeMaxDynamicSharedMemorySize,
                         GEMM_SMEM_BYTES);

    auto gemm = [&](const float* A, const float* Bm, const float* bias, const float* res,
                    float* C, int M, int N, int K, int dogelu) {
        dim3 g((N + 127) / 128, (M + 127) / 128);
        tf32gemm<<<g, 256, GEMM_SMEM_BYTES>>>(A, Bm, bias, res, C, M, N, K, dogelu);
    };

    // Patch embedding
    patch_gather<<<(MP_ * D_ + 255) / 256, 256>>>(x);
    gemm(patches, patch_w, patch_b, nullptr, hp, MP_, D_, D_, 0);
    assemble<<<(M_ * D_ + 255) / 256, 256>>>(cls_token, pos_emb);

    // Transformer blocks
    for (int l = 0; l < L_; l++) {
        const size_t wo = (size_t)l * D_ * D_;
        const size_t bo = (size_t)l * D_;

        ln_kernel<<<M_, 256>>>(h, ln1_w + bo, ln1_b + bo, z);
        gemm(z, wq + wo, bq + bo, nullptr, q, M_, D_, D_, 0);
        gemm(z, wk + wo, bk + bo, nullptr, k, M_, D_, D_, 0);
        gemm(z, wv + wo, bv + bo, nullptr, v, M_, D_, D_, 0);

        attn_fused<<<dim3(4, B_ * NH_), 256, ATTN_SMEM_BYTES>>>(q, k, v, y);

        gemm(y, wy + wo, by + bo, h, h, M_, D_, D_, 0);  // residual 1

        ln_kernel<<<M_, 256>>>(h, ln2_w + bo, ln2_b + bo, z);
        gemm(z, m1w + (size_t)l * D_ * FF_, m1b + (size_t)l * FF_, nullptr, mlp, M_, FF_, D_, 1);
        gemm(mlp, m2w + (size_t)l * FF_ * D_, m2b + bo, h, h, M_, D_, FF_, 0);  // residual 2
    }

    // Head
    cls_extract<<<(B_ * D_ + 255) / 256, 256>>>();
    ln_kernel<<<B_, 256>>>(cls, hlnw, hlnb, clsln);
    gemm(clsln, hw, hb, nullptr, out, B_, NC_, D_, 0);
}

// round 8
// speedup vs baseline: 3.4725x; 1.0023x over previous
#include <cuda_runtime.h>
#include <stdint.h>
#include <math.h>

// ---------------- Problem constants ----------------
#define B_   32
#define S_   197
#define NP_  196
#define D_   768
#define FF_  3072
#define L_   12
#define NH_  12
#define HD_  64
#define NC_  1000
#define M_   (B_ * S_)    // 6304
#define MP_  (B_ * NP_)   // 6272
#define EPS_ 1e-5f

// ---------------- Scratch (device globals; no allocs allowed) ----------------
__device__ float g_patches[(size_t)MP_ * D_];
__device__ float g_hp[(size_t)MP_ * D_];
__device__ float g_h[(size_t)M_ * D_];
__device__ float g_z[(size_t)M_ * D_];
__device__ float g_q[(size_t)M_ * D_];
__device__ float g_k[(size_t)M_ * D_];
__device__ float g_v[(size_t)M_ * D_];
__device__ float g_y[(size_t)M_ * D_];
__device__ float g_mlp[(size_t)M_ * FF_];
__device__ float g_cls[B_ * D_];
__device__ float g_clsln[B_ * D_];

// ---------------- Helpers ----------------
__device__ __forceinline__ float gelu_exact(float x) {
    return 0.5f * x * (1.0f + erff(x * 0.70710678118654752440f));
}

__device__ __forceinline__ unsigned f2tf(float f) {
    unsigned u;
    asm("cvt.rna.tf32.f32 %0, %1;" : "=r"(u) : "f"(f));
    return u;
}

__device__ __forceinline__ float blockReduceSum256(float v) {
    __shared__ float sh[8];
    int lane = threadIdx.x & 31, wid = threadIdx.x >> 5;
#pragma unroll
    for (int o = 16; o > 0; o >>= 1) v += __shfl_down_sync(0xffffffffu, v, o);
    if (lane == 0) sh[wid] = v;
    __syncthreads();
    if (wid == 0) {
        v = (lane < 8) ? sh[lane] : 0.0f;
#pragma unroll
        for (int o = 4; o > 0; o >>= 1) v += __shfl_down_sync(0xffffffffu, v, o);
        if (lane == 0) sh[0] = v;
    }
    __syncthreads();
    float r = sh[0];
    __syncthreads();
    return r;
}

// ---------------- TF32 tensor-core GEMM, cp.async 4-stage pipeline ----------------
// C[M,N] = A[M,K] @ B[K,N] + bias (+gelu) (+res)
// 128x128x16 block tile, 8 warps (2x4), 64x32 warp tile, m16n8k8 TF32 mma.
// Requires K % 16 == 0, N % 4 == 0.
#define GSTAGES 4
#define APAD 20   // floats per A row (16 + 4), conflict-free
#define BPAD 136  // floats per B k-row (128 + 8), conflict-free
#define STAGE_FLOATS (128 * APAD + 16 * BPAD)  // 2560 + 2176 = 4736
#define GEMM_SMEM_BYTES (GSTAGES * STAGE_FLOATS * 4)  // 75776

__device__ __forceinline__ void cp16(uint32_t dst, const void* src, int pred16) {
    asm volatile("cp.async.ca.shared.global [%0], [%1], 16, %2;"
                 :: "r"(dst), "l"(src), "r"(pred16));
}

__global__ __launch_bounds__(256) void tf32gemm(
    const float* __restrict__ A, const float* __restrict__ Bm,
    const float* __restrict__ bias, const float* __restrict__ res,
    float* __restrict__ C, int M, int N, int K, int dogelu)
{
    extern __shared__ float smem[];

    const int tid = threadIdx.x;
    const int warp = tid >> 5, lane = tid & 31;
    const int wm = warp >> 2, wn = warp & 3;      // warp grid 2x4
    const int gid = lane >> 2, tig = lane & 3;
    const int m0 = blockIdx.y * 128, n0 = blockIdx.x * 128;

    // per-thread copy coordinates (2 float4 each for A and B per stage)
    // A tile: 128 rows x 16 k-floats = 512 float4; lin>>2 = row, (lin&3)*4 = k col
    const int ar0 = tid >> 2,             ac0 = (tid & 3) * 4;   // lin = tid      -> rows 0..63
    const int ar1 = (tid + 256) >> 2,     ac1 = ac0;             // lin = tid+256  -> rows 64..127
    const int bk0 = tid >> 5,             bc0 = (tid & 31) * 4;  // B rows 0..7
    const int bk1 = (tid + 256) >> 5,     bc1 = bc0;             // B rows 8..15

    uint32_t smem_u32 = (uint32_t)__cvta_generic_to_shared(smem);

    auto issue_stage = [&](int k0, int buf) {
        uint32_t sa = smem_u32 + (uint32_t)(buf * STAGE_FLOATS) * 4u;
        uint32_t sb = sa + 128u * APAD * 4u;
        // A: rows ar, k cols k0+ac .. +3
        {
            int p = (m0 + ar0 < M) ? 16 : 0;
            cp16(sa + (uint32_t)(ar0 * APAD + ac0) * 4u,
                 A + (size_t)(m0 + ar0) * K + k0 + ac0, p);
            int p1 = (m0 + ar1 < M) ? 16 : 0;
            cp16(sa + (uint32_t)(ar1 * APAD + ac1) * 4u,
                 A + (size_t)(m0 + ar1) * K + k0 + ac1, p1);
        }
        // B: k rows k0+bk, n cols n0+bc .. +3
        {
            int gn = n0 + bc0;
            int p = (gn + 3 < N) ? 16 : 0;
            cp16(sb + (uint32_t)(bk0 * BPAD + bc0) * 4u,
                 Bm + (size_t)(k0 + bk0) * N + gn, p);
            int p1 = (gn + 3 < N) ? 16 : 0;
            cp16(sb + (uint32_t)(bk1 * BPAD + bc1) * 4u,
                 Bm + (size_t)(k0 + bk1) * N + gn, p1);
        }
        asm volatile("cp.async.commit_group;");
    };

    float acc[4][4][4];
#pragma unroll
    for (int i = 0; i < 4; i++)
#pragma unroll
        for (int j = 0; j < 4; j++)
#pragma unroll
            for (int c = 0; c < 4; c++) acc[i][j][c] = 0.0f;

    const int nk = K >> 4;

    // prologue: issue first GSTAGES-1 stages
#pragma unroll
    for (int s = 0; s < GSTAGES - 1; s++) {
        if (s < nk) issue_stage(s << 4, s);
        else asm volatile("cp.async.commit_group;");
    }

    for (int ch = 0; ch < nk; ch++) {
        asm volatile("cp.async.wait_group %0;" :: "n"(GSTAGES - 2));
        __syncthreads();

        // prefetch stage ch+GSTAGES-1 (writes buffer consumed at ch-1)
        int pf = ch + GSTAGES - 1;
        if (pf < nk) issue_stage(pf << 4, pf & (GSTAGES - 1));
        else asm volatile("cp.async.commit_group;");

        const float* sa = smem + (ch & (GSTAGES - 1)) * STAGE_FLOATS;
        const float* sb = sa + 128 * APAD;

#pragma unroll
        for (int kk = 0; kk < 2; kk++) {
            int k8 = kk * 8;
            unsigned af[4][4], bf[4][2];
#pragma unroll
            for (int mt = 0; mt < 4; mt++) {
                int mr = wm * 64 + mt * 16;
                af[mt][0] = f2tf(sa[(mr + gid) * APAD + k8 + tig]);
                af[mt][1] = f2tf(sa[(mr + gid + 8) * APAD + k8 + tig]);
                af[mt][2] = f2tf(sa[(mr + gid) * APAD + k8 + tig + 4]);
                af[mt][3] = f2tf(sa[(mr + gid + 8) * APAD + k8 + tig + 4]);
            }
#pragma unroll
            for (int nt = 0; nt < 4; nt++) {
                int nc = wn * 32 + nt * 8;
                bf[nt][0] = f2tf(sb[(k8 + tig) * BPAD + nc + gid]);
                bf[nt][1] = f2tf(sb[(k8 + tig + 4) * BPAD + nc + gid]);
            }
#pragma unroll
            for (int mt = 0; mt < 4; mt++)
#pragma unroll
                for (int nt = 0; nt < 4; nt++) {
                    asm volatile(
                        "mma.sync.aligned.m16n8k8.row.col.f32.tf32.tf32.f32 "
                        "{%0,%1,%2,%3}, {%4,%5,%6,%7}, {%8,%9}, {%0,%1,%2,%3};"
                        : "+f"(acc[mt][nt][0]), "+f"(acc[mt][nt][1]),
                          "+f"(acc[mt][nt][2]), "+f"(acc[mt][nt][3])
                        : "r"(af[mt][0]), "r"(af[mt][1]), "r"(af[mt][2]), "r"(af[mt][3]),
                          "r"(bf[nt][0]), "r"(bf[nt][1]));
                }
        }
        __syncthreads();
    }

    // Epilogue
    auto emit = [&](int r, int c, float v0, float v1) {
        if (r >= M) return;
        if (c + 1 < N) {
            float2 o;
            o.x = v0 + bias[c];
            o.y = v1 + bias[c + 1];
            if (dogelu) { o.x = gelu_exact(o.x); o.y = gelu_exact(o.y); }
            if (res) {
                float2 rr = *reinterpret_cast<const float2*>(res + (size_t)r * N + c);
                o.x += rr.x; o.y += rr.y;
            }
            *reinterpret_cast<float2*>(C + (size_t)r * N + c) = o;
        } else if (c < N) {
            float v = v0 + bias[c];
            if (dogelu) v = gelu_exact(v);
            if (res) v += res[(size_t)r * N + c];
            C[(size_t)r * N + c] = v;
        }
    };

#pragma unroll
    for (int mt = 0; mt < 4; mt++) {
        int r0 = m0 + wm * 64 + mt * 16 + gid;
#pragma unroll
        for (int nt = 0; nt < 4; nt++) {
            int c0 = n0 + wn * 32 + nt * 8 + 2 * tig;
            emit(r0,     c0, acc[mt][nt][0], acc[mt][nt][1]);
            emit(r0 + 8, c0, acc[mt][nt][2], acc[mt][nt][3]);
        }
    }
}

// ---------------- Fused attention (exact fp32) ----------------
#define ATTN_SMEM_FLOATS (64 * 68 * 2 + 64 * 201 + 64)
#define ATTN_SMEM_BYTES  (ATTN_SMEM_FLOATS * 4)

__global__ __launch_bounds__(256) void attn_fused(
    const float* __restrict__ q, const float* __restrict__ k,
    const float* __restrict__ v, float* __restrict__ y)
{
    extern __shared__ float smattn[];
    float* QsT = smattn;                 // [64][68] indexed [d][row]
    float* KVs = smattn + 4352;          // [64][68]
    float* Sb  = smattn + 8704;          // [64][201]
    float* rowl = smattn + 8704 + 64 * 201;

    const int tid = threadIdx.x;
    const int ty = tid >> 4, tx = tid & 15;
    const int bh = blockIdx.y;
    const int b = bh / NH_, h = bh % NH_;
    const int q0 = blockIdx.x * 64;

#pragma unroll
    for (int i = 0; i < 4; i++) {
        int lin = tid + i * 256;
        int row = lin >> 4, c4 = (lin & 15) * 4;
        float4 val = make_float4(0.f, 0.f, 0.f, 0.f);
        int gr = q0 + row;
        if (gr < S_)
            val = *reinterpret_cast<const float4*>(q + (size_t)(b * S_ + gr) * D_ + h * HD_ + c4);
        QsT[(c4 + 0) * 68 + row] = val.x;
        QsT[(c4 + 1) * 68 + row] = val.y;
        QsT[(c4 + 2) * 68 + row] = val.z;
        QsT[(c4 + 3) * 68 + row] = val.w;
    }
    __syncthreads();

    for (int j0 = 0; j0 < S_; j0 += 64) {
#pragma unroll
        for (int i = 0; i < 4; i++) {
            int lin = tid + i * 256;
            int row = lin >> 4, c4 = (lin & 15) * 4;
            float4 val = make_float4(0.f, 0.f, 0.f, 0.f);
            int gr = j0 + row;
            if (gr < S_)
                val = *reinterpret_cast<const float4*>(k + (size_t)(b * S_ + gr) * D_ + h * HD_ + c4);
            KVs[(c4 + 0) * 68 + row] = val.x;
            KVs[(c4 + 1) * 68 + row] = val.y;
            KVs[(c4 + 2) * 68 + row] = val.z;
            KVs[(c4 + 3) * 68 + row] = val.w;
        }
        __syncthreads();

        float acc[4][4];
#pragma unroll
        for (int i = 0; i < 4; i++)
#pragma unroll
            for (int j = 0; j < 4; j++) acc[i][j] = 0.0f;

#pragma unroll 8
        for (int d = 0; d < HD_; d++) {
            float4 a = *reinterpret_cast<const float4*>(&QsT[d * 68 + ty * 4]);
            float4 bb = *reinterpret_cast<const float4*>(&KVs[d * 68 + tx * 4]);
            float av[4] = {a.x, a.y, a.z, a.w};
            float bv[4] = {bb.x, bb.y, bb.z, bb.w};
#pragma unroll
            for (int i = 0; i < 4; i++)
#pragma unroll
                for (int j = 0; j < 4; j++) acc[i][j] = fmaf(av[i], bv[j], acc[i][j]);
        }

#pragma unroll
        for (int i = 0; i < 4; i++)
#pragma unroll
            for (int j = 0; j < 4; j++) {
                int col = j0 + tx * 4 + j;
                if (col < S_) Sb[(ty * 4 + i) * 201 + col] = acc[i][j] * 0.125f;
            }
        __syncthreads();
    }

    {
        int row = tid >> 2, seg = tid & 3;
        float* sr = Sb + row * 201;
        float m = -3.0e38f;
        for (int c = seg; c < S_; c += 4) m = fmaxf(m, sr[c]);
        m = fmaxf(m, __shfl_xor_sync(0xffffffffu, m, 1));
        m = fmaxf(m, __shfl_xor_sync(0xffffffffu, m, 2));
        float l = 0.0f;
        for (int c = seg; c < S_; c += 4) {
            float e = expf(sr[c] - m);
            sr[c] = e;
            l += e;
        }
        l += __shfl_xor_sync(0xffffffffu, l, 1);
        l += __shfl_xor_sync(0xffffffffu, l, 2);
        if (seg == 0) rowl[row] = l;
    }
    __syncthreads();

    float o[4][4];
#pragma unroll
    for (int i = 0; i < 4; i++)
#pragma unroll
        for (int j = 0; j < 4; j++) o[i][j] = 0.0f;

    for (int j0 = 0; j0 < S_; j0 += 64) {
#pragma unroll
        for (int i = 0; i < 4; i++) {
            int lin = tid + i * 256;
            int row = lin >> 4, c4 = (lin & 15) * 4;
            float4 val = make_float4(0.f, 0.f, 0.f, 0.f);
            int gr = j0 + row;
            if (gr < S_)
                val = *reinterpret_cast<const float4*>(v + (size_t)(b * S_ + gr) * D_ + h * HD_ + c4);
            *reinterpret_cast<float4*>(&KVs[row * 68 + c4]) = val;
        }
        __syncthreads();

        int jmax = (S_ - j0 < 64) ? (S_ - j0) : 64;
#pragma unroll 8
        for (int jj = 0; jj < jmax; jj++) {
            float4 bb = *reinterpret_cast<const float4*>(&KVs[jj * 68 + tx * 4]);
            float bv[4] = {bb.x, bb.y, bb.z, bb.w};
            float av[4];
#pragma unroll
            for (int i = 0; i < 4; i++) av[i] = Sb[(ty * 4 + i) * 201 + j0 + jj];
#pragma unroll
            for (int i = 0; i < 4; i++)
#pragma unroll
                for (int j = 0; j < 4; j++) o[i][j] = fmaf(av[i], bv[j], o[i][j]);
        }
        __syncthreads();
    }

#pragma unroll
    for (int i = 0; i < 4; i++) {
        int gr = q0 + ty * 4 + i;
        if (gr < S_) {
            float linv = 1.0f / rowl[ty * 4 + i];
            float4 ov = make_float4(o[i][0] * linv, o[i][1] * linv,
                                    o[i][2] * linv, o[i][3] * linv);
            *reinterpret_cast<float4*>(y + (size_t)(b * S_ + gr) * D_ + h * HD_ + tx * 4) = ov;
        }
    }
}

// ---------------- LayerNorm ----------------
__global__ __launch_bounds__(256) void ln_kernel(
    const float* __restrict__ x, const float* __restrict__ w,
    const float* __restrict__ b, float* __restrict__ out)
{
    __shared__ float row[D_];
    int m = blockIdx.x;
    const float* xr = x + (size_t)m * D_;
    float s = 0.0f;
    for (int d = threadIdx.x; d < D_; d += 256) {
        float v = xr[d];
        row[d] = v;
        s += v;
    }
    __syncthreads();
    s = blockReduceSum256(s);
    float mean = s * (1.0f / D_);
    float s2 = 0.0f;
    for (int d = threadIdx.x; d < D_; d += 256) {
        float v = row[d] - mean;
        s2 += v * v;
    }
    s2 = blockReduceSum256(s2);
    float inv = 1.0f / (sqrtf(s2 * (1.0f / D_)) + EPS_);
    float* op = out + (size_t)m * D_;
    for (int d = threadIdx.x; d < D_; d += 256)
        op[d] = (row[d] - mean) * inv * w[d] + b[d];
}

// ---------------- Patch gather ----------------
__global__ void patch_gather(const float* __restrict__ x)
{
    int idx = blockIdx.x * blockDim.x + threadIdx.x;
    if (idx >= MP_ * D_) return;
    int r = idx / D_, kk = idx - r * D_;
    int b = r / NP_, p = r - b * NP_;
    int ph = p / 14, pw = p - ph * 14;
    int c = kk >> 8;
    int rem = kk & 255;
    int pi = rem >> 4, pj = rem & 15;
    g_patches[idx] = x[((size_t)(b * 3 + c) * 224 + ph * 16 + pi) * 224 + pw * 16 + pj];
}

// ---------------- Assemble h ----------------
__global__ void assemble(const float* __restrict__ cls_token, const float* __restrict__ pos)
{
    int idx = blockIdx.x * blockDim.x + threadIdx.x;
    if (idx >= M_ * D_) return;
    int m = idx / D_, d = idx - m * D_;
    int b = m / S_, s = m - b * S_;
    float val;
    if (s == 0)
        val = cls_token[d] + pos[d];
    else
        val = g_hp[((size_t)b * NP_ + (s - 1)) * D_ + d] + pos[(size_t)s * D_ + d];
    g_h[idx] = val;
}

// ---------------- Extract CLS rows ----------------
__global__ void cls_extract()
{
    int idx = blockIdx.x * blockDim.x + threadIdx.x;
    if (idx >= B_ * D_) return;
    int b = idx / D_, d = idx - b * D_;
    g_cls[idx] = g_h[((size_t)b * S_) * D_ + d];
}

// ---------------- Host orchestration ----------------
extern "C" void kernel_launch(void* const* d_in, const int* in_sizes, int n_in,
                              void* d_out, int out_size)
{
    (void)in_sizes; (void)n_in; (void)out_size;
    const float* x         = (const float*)d_in[0];
    const float* patch_w   = (const float*)d_in[1];
    const float* patch_b   = (const float*)d_in[2];
    const float* cls_token = (const float*)d_in[3];
    const float* pos_emb   = (const float*)d_in[4];
    const float* ln1_w     = (const float*)d_in[5];
    const float* ln1_b     = (const float*)d_in[6];
    const float* wq        = (const float*)d_in[7];
    const float* bq        = (const float*)d_in[8];
    const float* wk        = (const float*)d_in[9];
    const float* bk        = (const float*)d_in[10];
    const float* wv        = (const float*)d_in[11];
    const float* bv        = (const float*)d_in[12];
    const float* wy        = (const float*)d_in[13];
    const float* by        = (const float*)d_in[14];
    const float* ln2_w     = (const float*)d_in[15];
    const float* ln2_b     = (const float*)d_in[16];
    const float* m1w       = (const float*)d_in[17];
    const float* m1b       = (const float*)d_in[18];
    const float* m2w       = (const float*)d_in[19];
    const float* m2b       = (const float*)d_in[20];
    const float* hlnw      = (const float*)d_in[21];
    const float* hlnb      = (const float*)d_in[22];
    const float* hw        = (const float*)d_in[23];
    const float* hb        = (const float*)d_in[24];
    float* out = (float*)d_out;

    float *patches, *hp, *h, *z, *q, *k, *v, *y, *mlp, *cls, *clsln;
    cudaGetSymbolAddress((void**)&patches, g_patches);
    cudaGetSymbolAddress((void**)&hp, g_hp);
    cudaGetSymbolAddress((void**)&h, g_h);
    cudaGetSymbolAddress((void**)&z, g_z);
    cudaGetSymbolAddress((void**)&q, g_q);
    cudaGetSymbolAddress((void**)&k, g_k);
    cudaGetSymbolAddress((void**)&v, g_v);
    cudaGetSymbolAddress((void**)&y, g_y);
    cudaGetSymbolAddress((void**)&mlp, g_mlp);
    cudaGetSymbolAddress((void**)&cls, g_cls);
    cudaGetSymbolAddress((void**)&clsln, g_clsln);

    cudaFuncSetAttribute(attn_fused, cudaFuncAttributeMaxDynamicSharedMemorySize,
                         ATTN_SMEM_BYTES);
    cudaFuncSetAttribute(tf32gemm, cudaFuncAttributeMaxDynamicSharedMemorySize,
                         GEMM_SMEM_BYTES);

    auto gemm = [&](const float* A, const float* Bm, const float* bias, const float* res,
                    float* C, int M, int N, int K, int dogelu) {
        dim3 g((N + 127) / 128, (M + 127) / 128);
        tf32gemm<<<g, 256, GEMM_SMEM_BYTES>>>(A, Bm, bias, res, C, M, N, K, dogelu);
    };

    // Patch embedding
    patch_gather<<<(MP_ * D_ + 255) / 256, 256>>>(x);
    gemm(patches, patch_w, patch_b, nullptr, hp, MP_, D_, D_, 0);
    assemble<<<(M_ * D_ + 255) / 256, 256>>>(cls_token, pos_emb);

    // Transformer blocks
    for (int l = 0; l < L_; l++) {
        const size_t wo = (size_t)l * D_ * D_;
        const size_t bo = (size_t)l * D_;

        ln_kernel<<<M_, 256>>>(h, ln1_w + bo, ln1_b + bo, z);
        gemm(z, wq + wo, bq + bo, nullptr, q, M_, D_, D_, 0);
        gemm(z, wk + wo, bk + bo, nullptr, k, M_, D_, D_, 0);
        gemm(z, wv + wo, bv + bo, nullptr, v, M_, D_, D_, 0);

        attn_fused<<<dim3(4, B_ * NH_), 256, ATTN_SMEM_BYTES>>>(q, k, v, y);

        gemm(y, wy + wo, by + bo, h, h, M_, D_, D_, 0);  // residual 1

        ln_kernel<<<M_, 256>>>(h, ln2_w + bo, ln2_b + bo, z);
        gemm(z, m1w + (size_t)l * D_ * FF_, m1b + (size_t)l * FF_, nullptr, mlp, M_, FF_, D_, 1);
        gemm(mlp, m2w + (size_t)l * FF_ * D_, m2b + bo, h, h, M_, D_, FF_, 0);  // residual 2
    }

    // Head
    cls_extract<<<(B_ * D_ + 255) / 256, 256>>>();
    ln_kernel<<<B_, 256>>>(cls, hlnw, hlnb, clsln);
    gemm(clsln, hw, hb, nullptr, out, B_, NC_, D_, 0);
}

// round 9
// speedup vs baseline: 3.4782x; 1.0016x over previous
#include <cuda_runtime.h>
#include <stdint.h>
#include <math.h>

// ---------------- Problem constants ----------------
#define B_   32
#define S_   197
#define NP_  196
#define D_   768
#define FF_  3072
#define L_   12
#define NH_  12
#define HD_  64
#define NC_  1000
#define M_   (B_ * S_)    // 6304
#define MP_  (B_ * NP_)   // 6272
#define EPS_ 1e-5f

// ---------------- Scratch (device globals; no allocs allowed) ----------------
__device__ float g_patches[(size_t)MP_ * D_];
__device__ float g_hp[(size_t)MP_ * D_];
__device__ float g_h[(size_t)M_ * D_];
__device__ float g_z[(size_t)M_ * D_];
__device__ float g_q[(size_t)M_ * D_];
__device__ float g_k[(size_t)M_ * D_];
__device__ float g_v[(size_t)M_ * D_];
__device__ float g_y[(size_t)M_ * D_];
__device__ float g_mlp[(size_t)M_ * FF_];
__device__ float g_cls[B_ * D_];
__device__ float g_clsln[B_ * D_];

// ---------------- Helpers ----------------
__device__ __forceinline__ float gelu_exact(float x) {
    return 0.5f * x * (1.0f + erff(x * 0.70710678118654752440f));
}

__device__ __forceinline__ unsigned f2tf(float f) {
    unsigned u;
    asm("cvt.rna.tf32.f32 %0, %1;" : "=r"(u) : "f"(f));
    return u;
}

__device__ __forceinline__ float blockReduceSum256(float v) {
    __shared__ float sh[8];
    int lane = threadIdx.x & 31, wid = threadIdx.x >> 5;
#pragma unroll
    for (int o = 16; o > 0; o >>= 1) v += __shfl_down_sync(0xffffffffu, v, o);
    if (lane == 0) sh[wid] = v;
    __syncthreads();
    if (wid == 0) {
        v = (lane < 8) ? sh[lane] : 0.0f;
#pragma unroll
        for (int o = 4; o > 0; o >>= 1) v += __shfl_down_sync(0xffffffffu, v, o);
        if (lane == 0) sh[0] = v;
    }
    __syncthreads();
    float r = sh[0];
    __syncthreads();
    return r;
}

// ---------------- TF32 tensor-core GEMM, cp.async 4-stage pipeline ----------------
// C[M,N] = A[M,K] @ B[K,N] + bias (+gelu) (+res)
// 128x128x16 block tile, 8 warps (2x4), 64x32 warp tile, m16n8k8 TF32 mma.
// Requires K % 16 == 0, N % 4 == 0.
#define GSTAGES 4
#define APAD 20   // floats per A row (16 + 4), conflict-free
#define BPAD 136  // floats per B k-row (128 + 8), conflict-free
#define STAGE_FLOATS (128 * APAD + 16 * BPAD)  // 2560 + 2176 = 4736
#define GEMM_SMEM_BYTES (GSTAGES * STAGE_FLOATS * 4)  // 75776

__device__ __forceinline__ void cp16(uint32_t dst, const void* src, int pred16) {
    asm volatile("cp.async.ca.shared.global [%0], [%1], 16, %2;"
                 :: "r"(dst), "l"(src), "r"(pred16));
}

__global__ __launch_bounds__(256) void tf32gemm(
    const float* __restrict__ A, const float* __restrict__ Bm,
    const float* __restrict__ bias, const float* __restrict__ res,
    float* __restrict__ C, int M, int N, int K, int dogelu)
{
    extern __shared__ float smem[];

    const int tid = threadIdx.x;
    const int warp = tid >> 5, lane = tid & 31;
    const int wm = warp >> 2, wn = warp & 3;      // warp grid 2x4
    const int gid = lane >> 2, tig = lane & 3;
    const int m0 = blockIdx.y * 128, n0 = blockIdx.x * 128;

    // per-thread copy coordinates (2 float4 each for A and B per stage)
    // A tile: 128 rows x 16 k-floats = 512 float4; lin>>2 = row, (lin&3)*4 = k col
    const int ar0 = tid >> 2,             ac0 = (tid & 3) * 4;   // lin = tid      -> rows 0..63
    const int ar1 = (tid + 256) >> 2,     ac1 = ac0;             // lin = tid+256  -> rows 64..127
    const int bk0 = tid >> 5,             bc0 = (tid & 31) * 4;  // B rows 0..7
    const int bk1 = (tid + 256) >> 5,     bc1 = bc0;             // B rows 8..15

    uint32_t smem_u32 = (uint32_t)__cvta_generic_to_shared(smem);

    auto issue_stage = [&](int k0, int buf) {
        uint32_t sa = smem_u32 + (uint32_t)(buf * STAGE_FLOATS) * 4u;
        uint32_t sb = sa + 128u * APAD * 4u;
        // A: rows ar, k cols k0+ac .. +3
        {
            int p = (m0 + ar0 < M) ? 16 : 0;
            cp16(sa + (uint32_t)(ar0 * APAD + ac0) * 4u,
                 A + (size_t)(m0 + ar0) * K + k0 + ac0, p);
            int p1 = (m0 + ar1 < M) ? 16 : 0;
            cp16(sa + (uint32_t)(ar1 * APAD + ac1) * 4u,
                 A + (size_t)(m0 + ar1) * K + k0 + ac1, p1);
        }
        // B: k rows k0+bk, n cols n0+bc .. +3
        {
            int gn = n0 + bc0;
            int p = (gn + 3 < N) ? 16 : 0;
            cp16(sb + (uint32_t)(bk0 * BPAD + bc0) * 4u,
                 Bm + (size_t)(k0 + bk0) * N + gn, p);
            int p1 = (gn + 3 < N) ? 16 : 0;
            cp16(sb + (uint32_t)(bk1 * BPAD + bc1) * 4u,
                 Bm + (size_t)(k0 + bk1) * N + gn, p1);
        }
        asm volatile("cp.async.commit_group;");
    };

    float acc[4][4][4];
#pragma unroll
    for (int i = 0; i < 4; i++)
#pragma unroll
        for (int j = 0; j < 4; j++)
#pragma unroll
            for (int c = 0; c < 4; c++) acc[i][j][c] = 0.0f;

    const int nk = K >> 4;

    // prologue: issue first GSTAGES-1 stages
#pragma unroll
    for (int s = 0; s < GSTAGES - 1; s++) {
        if (s < nk) issue_stage(s << 4, s);
        else asm volatile("cp.async.commit_group;");
    }

    for (int ch = 0; ch < nk; ch++) {
        asm volatile("cp.async.wait_group %0;" :: "n"(GSTAGES - 2));
        __syncthreads();

        // prefetch stage ch+GSTAGES-1 (writes buffer consumed at ch-1)
        int pf = ch + GSTAGES - 1;
        if (pf < nk) issue_stage(pf << 4, pf & (GSTAGES - 1));
        else asm volatile("cp.async.commit_group;");

        const float* sa = smem + (ch & (GSTAGES - 1)) * STAGE_FLOATS;
        const float* sb = sa + 128 * APAD;

#pragma unroll
        for (int kk = 0; kk < 2; kk++) {
            int k8 = kk * 8;
            unsigned af[4][4], bf[4][2];
#pragma unroll
            for (int mt = 0; mt < 4; mt++) {
                int mr = wm * 64 + mt * 16;
                af[mt][0] = f2tf(sa[(mr + gid) * APAD + k8 + tig]);
                af[mt][1] = f2tf(sa[(mr + gid + 8) * APAD + k8 + tig]);
                af[mt][2] = f2tf(sa[(mr + gid) * APAD + k8 + tig + 4]);
                af[mt][3] = f2tf(sa[(mr + gid + 8) * APAD + k8 + tig + 4]);
            }
#pragma unroll
            for (int nt = 0; nt < 4; nt++) {
                int nc = wn * 32 + nt * 8;
                bf[nt][0] = f2tf(sb[(k8 + tig) * BPAD + nc + gid]);
                bf[nt][1] = f2tf(sb[(k8 + tig + 4) * BPAD + nc + gid]);
            }
#pragma unroll
            for (int mt = 0; mt < 4; mt++)
#pragma unroll
                for (int nt = 0; nt < 4; nt++) {
                    asm volatile(
                        "mma.sync.aligned.m16n8k8.row.col.f32.tf32.tf32.f32 "
                        "{%0,%1,%2,%3}, {%4,%5,%6,%7}, {%8,%9}, {%0,%1,%2,%3};"
                        : "+f"(acc[mt][nt][0]), "+f"(acc[mt][nt][1]),
                          "+f"(acc[mt][nt][2]), "+f"(acc[mt][nt][3])
                        : "r"(af[mt][0]), "r"(af[mt][1]), "r"(af[mt][2]), "r"(af[mt][3]),
                          "r"(bf[nt][0]), "r"(bf[nt][1]));
                }
        }
        __syncthreads();
    }

    // Epilogue
    auto emit = [&](int r, int c, float v0, float v1) {
        if (r >= M) return;
        if (c + 1 < N) {
            float2 o;
            o.x = v0 + bias[c];
            o.y = v1 + bias[c + 1];
            if (dogelu) { o.x = gelu_exact(o.x); o.y = gelu_exact(o.y); }
            if (res) {
                float2 rr = *reinterpret_cast<const float2*>(res + (size_t)r * N + c);
                o.x += rr.x; o.y += rr.y;
            }
            *reinterpret_cast<float2*>(C + (size_t)r * N + c) = o;
        } else if (c < N) {
            float v = v0 + bias[c];
            if (dogelu) v = gelu_exact(v);
            if (res) v += res[(size_t)r * N + c];
            C[(size_t)r * N + c] = v;
        }
    };

#pragma unroll
    for (int mt = 0; mt < 4; mt++) {
        int r0 = m0 + wm * 64 + mt * 16 + gid;
#pragma unroll
        for (int nt = 0; nt < 4; nt++) {
            int c0 = n0 + wn * 32 + nt * 8 + 2 * tig;
            emit(r0,     c0, acc[mt][nt][0], acc[mt][nt][1]);
            emit(r0 + 8, c0, acc[mt][nt][2], acc[mt][nt][3]);
        }
    }
}

// ---------------- Fused attention (exact fp32) ----------------
#define ATTN_SMEM_FLOATS (64 * 68 * 2 + 64 * 201 + 64)
#define ATTN_SMEM_BYTES  (ATTN_SMEM_FLOATS * 4)

__global__ __launch_bounds__(256) void attn_fused(
    const float* __restrict__ q, const float* __restrict__ k,
    const float* __restrict__ v, float* __restrict__ y)
{
    extern __shared__ float smattn[];
    float* QsT = smattn;                 // [64][68] indexed [d][row]
    float* KVs = smattn + 4352;          // [64][68]
    float* Sb  = smattn + 8704;          // [64][201]
    float* rowl = smattn + 8704 + 64 * 201;

    const int tid = threadIdx.x;
    const int ty = tid >> 4, tx = tid & 15;
    const int bh = blockIdx.y;
    const int b = bh / NH_, h = bh % NH_;
    const int q0 = blockIdx.x * 64;

#pragma unroll
    for (int i = 0; i < 4; i++) {
        int lin = tid + i * 256;
        int row = lin >> 4, c4 = (lin & 15) * 4;
        float4 val = make_float4(0.f, 0.f, 0.f, 0.f);
        int gr = q0 + row;
        if (gr < S_)
            val = *reinterpret_cast<const float4*>(q + (size_t)(b * S_ + gr) * D_ + h * HD_ + c4);
        QsT[(c4 + 0) * 68 + row] = val.x;
        QsT[(c4 + 1) * 68 + row] = val.y;
        QsT[(c4 + 2) * 68 + row] = val.z;
        QsT[(c4 + 3) * 68 + row] = val.w;
    }
    __syncthreads();

    for (int j0 = 0; j0 < S_; j0 += 64) {
#pragma unroll
        for (int i = 0; i < 4; i++) {
            int lin = tid + i * 256;
            int row = lin >> 4, c4 = (lin & 15) * 4;
            float4 val = make_float4(0.f, 0.f, 0.f, 0.f);
            int gr = j0 + row;
            if (gr < S_)
                val = *reinterpret_cast<const float4*>(k + (size_t)(b * S_ + gr) * D_ + h * HD_ + c4);
            KVs[(c4 + 0) * 68 + row] = val.x;
            KVs[(c4 + 1) * 68 + row] = val.y;
            KVs[(c4 + 2) * 68 + row] = val.z;
            KVs[(c4 + 3) * 68 + row] = val.w;
        }
        __syncthreads();

        float acc[4][4];
#pragma unroll
        for (int i = 0; i < 4; i++)
#pragma unroll
            for (int j = 0; j < 4; j++) acc[i][j] = 0.0f;

#pragma unroll 8
        for (int d = 0; d < HD_; d++) {
            float4 a = *reinterpret_cast<const float4*>(&QsT[d * 68 + ty * 4]);
            float4 bb = *reinterpret_cast<const float4*>(&KVs[d * 68 + tx * 4]);
            float av[4] = {a.x, a.y, a.z, a.w};
            float bv[4] = {bb.x, bb.y, bb.z, bb.w};
#pragma unroll
            for (int i = 0; i < 4; i++)
#pragma unroll
                for (int j = 0; j < 4; j++) acc[i][j] = fmaf(av[i], bv[j], acc[i][j]);
        }

#pragma unroll
        for (int i = 0; i < 4; i++)
#pragma unroll
            for (int j = 0; j < 4; j++) {
                int col = j0 + tx * 4 + j;
                if (col < S_) Sb[(ty * 4 + i) * 201 + col] = acc[i][j] * 0.125f;
            }
        __syncthreads();
    }

    {
        int row = tid >> 2, seg = tid & 3;
        float* sr = Sb + row * 201;
        float m = -3.0e38f;
        for (int c = seg; c < S_; c += 4) m = fmaxf(m, sr[c]);
        m = fmaxf(m, __shfl_xor_sync(0xffffffffu, m, 1));
        m = fmaxf(m, __shfl_xor_sync(0xffffffffu, m, 2));
        float l = 0.0f;
        for (int c = seg; c < S_; c += 4) {
            float e = expf(sr[c] - m);
            sr[c] = e;
            l += e;
        }
        l += __shfl_xor_sync(0xffffffffu, l, 1);
        l += __shfl_xor_sync(0xffffffffu, l, 2);
        if (seg == 0) rowl[row] = l;
    }
    __syncthreads();

    float o[4][4];
#pragma unroll
    for (int i = 0; i < 4; i++)
#pragma unroll
        for (int j = 0; j < 4; j++) o[i][j] = 0.0f;

    for (int j0 = 0; j0 < S_; j0 += 64) {
#pragma unroll
        for (int i = 0; i < 4; i++) {
            int lin = tid + i * 256;
            int row = lin >> 4, c4 = (lin & 15) * 4;
            float4 val = make_float4(0.f, 0.f, 0.f, 0.f);
            int gr = j0 + row;
            if (gr < S_)
                val = *reinterpret_cast<const float4*>(v + (size_t)(b * S_ + gr) * D_ + h * HD_ + c4);
            *reinterpret_cast<float4*>(&KVs[row * 68 + c4]) = val;
        }
        __syncthreads();

        int jmax = (S_ - j0 < 64) ? (S_ - j0) : 64;
#pragma unroll 8
        for (int jj = 0; jj < jmax; jj++) {
            float4 bb = *reinterpret_cast<const float4*>(&KVs[jj * 68 + tx * 4]);
            float bv[4] = {bb.x, bb.y, bb.z, bb.w};
            float av[4];
#pragma unroll
            for (int i = 0; i < 4; i++) av[i] = Sb[(ty * 4 + i) * 201 + j0 + jj];
#pragma unroll
            for (int i = 0; i < 4; i++)
#pragma unroll
                for (int j = 0; j < 4; j++) o[i][j] = fmaf(av[i], bv[j], o[i][j]);
        }
        __syncthreads();
    }

#pragma unroll
    for (int i = 0; i < 4; i++) {
        int gr = q0 + ty * 4 + i;
        if (gr < S_) {
            float linv = 1.0f / rowl[ty * 4 + i];
            float4 ov = make_float4(o[i][0] * linv, o[i][1] * linv,
                                    o[i][2] * linv, o[i][3] * linv);
            *reinterpret_cast<float4*>(y + (size_t)(b * S_ + gr) * D_ + h * HD_ + tx * 4) = ov;
        }
    }
}

// ---------------- LayerNorm ----------------
__global__ __launch_bounds__(256) void ln_kernel(
    const float* __restrict__ x, const float* __restrict__ w,
    const float* __restrict__ b, float* __restrict__ out)
{
    __shared__ float row[D_];
    int m = blockIdx.x;
    const float* xr = x + (size_t)m * D_;
    float s = 0.0f;
    for (int d = threadIdx.x; d < D_; d += 256) {
        float v = xr[d];
        row[d] = v;
        s += v;
    }
    __syncthreads();
    s = blockReduceSum256(s);
    float mean = s * (1.0f / D_);
    float s2 = 0.0f;
    for (int d = threadIdx.x; d < D_; d += 256) {
        float v = row[d] - mean;
        s2 += v * v;
    }
    s2 = blockReduceSum256(s2);
    float inv = 1.0f / (sqrtf(s2 * (1.0f / D_)) + EPS_);
    float* op = out + (size_t)m * D_;
    for (int d = threadIdx.x; d < D_; d += 256)
        op[d] = (row[d] - mean) * inv * w[d] + b[d];
}

// ---------------- Patch gather ----------------
__global__ void patch_gather(const float* __restrict__ x)
{
    int idx = blockIdx.x * blockDim.x + threadIdx.x;
    if (idx >= MP_ * D_) return;
    int r = idx / D_, kk = idx - r * D_;
    int b = r / NP_, p = r - b * NP_;
    int ph = p / 14, pw = p - ph * 14;
    int c = kk >> 8;
    int rem = kk & 255;
    int pi = rem >> 4, pj = rem & 15;
    g_patches[idx] = x[((size_t)(b * 3 + c) * 224 + ph * 16 + pi) * 224 + pw * 16 + pj];
}

// ---------------- Assemble h ----------------
__global__ void assemble(const float* __restrict__ cls_token, const float* __restrict__ pos)
{
    int idx = blockIdx.x * blockDim.x + threadIdx.x;
    if (idx >= M_ * D_) return;
    int m = idx / D_, d = idx - m * D_;
    int b = m / S_, s = m - b * S_;
    float val;
    if (s == 0)
        val = cls_token[d] + pos[d];
    else
        val = g_hp[((size_t)b * NP_ + (s - 1)) * D_ + d] + pos[(size_t)s * D_ + d];
    g_h[idx] = val;
}

// ---------------- Extract CLS rows ----------------
__global__ void cls_extract()
{
    int idx = blockIdx.x * blockDim.x + threadIdx.x;
    if (idx >= B_ * D_) return;
    int b = idx / D_, d = idx - b * D_;
    g_cls[idx] = g_h[((size_t)b * S_) * D_ + d];
}

// ---------------- Host orchestration ----------------
extern "C" void kernel_launch(void* const* d_in, const int* in_sizes, int n_in,
                              void* d_out, int out_size)
{
    (void)in_sizes; (void)n_in; (void)out_size;
    const float* x         = (const float*)d_in[0];
    const float* patch_w   = (const float*)d_in[1];
    const float* patch_b   = (const float*)d_in[2];
    const float* cls_token = (const float*)d_in[3];
    const float* pos_emb   = (const float*)d_in[4];
    const float* ln1_w     = (const float*)d_in[5];
    const float* ln1_b     = (const float*)d_in[6];
    const float* wq        = (const float*)d_in[7];
    const float* bq        = (const float*)d_in[8];
    const float* wk        = (const float*)d_in[9];
    const float* bk        = (const float*)d_in[10];
    const float* wv        = (const float*)d_in[11];
    const float* bv        = (const float*)d_in[12];
    const float* wy        = (const float*)d_in[13];
    const float* by        = (const float*)d_in[14];
    const float* ln2_w     = (const float*)d_in[15];
    const float* ln2_b     = (const float*)d_in[16];
    const float* m1w       = (const float*)d_in[17];
    const float* m1b       = (const float*)d_in[18];
    const float* m2w       = (const float*)d_in[19];
    const float* m2b       = (const float*)d_in[20];
    const float* hlnw      = (const float*)d_in[21];
    const float* hlnb      = (const float*)d_in[22];
    const float* hw        = (const float*)d_in[23];
    const float* hb        = (const float*)d_in[24];
    float* out = (float*)d_out;

    float *patches, *hp, *h, *z, *q, *k, *v, *y, *mlp, *cls, *clsln;
    cudaGetSymbolAddress((void**)&patches, g_patches);
    cudaGetSymbolAddress((void**)&hp, g_hp);
    cudaGetSymbolAddress((void**)&h, g_h);
    cudaGetSymbolAddress((void**)&z, g_z);
    cudaGetSymbolAddress((void**)&q, g_q);
    cudaGetSymbolAddress((void**)&k, g_k);
    cudaGetSymbolAddress((void**)&v, g_v);
    cudaGetSymbolAddress((void**)&y, g_y);
    cudaGetSymbolAddress((void**)&mlp, g_mlp);
    cudaGetSymbolAddress((void**)&cls, g_cls);
    cudaGetSymbolAddress((void**)&clsln, g_clsln);

    cudaFuncSetAttribute(attn_fused, cudaFuncAttributeMaxDynamicSharedMemorySize,
                         ATTN_SMEM_BYTES);
    cudaFuncSetAttribute(tf32gemm, cudaFuncAttributeMaxDynamicSharedMemorySize,
                         GEMM_SMEM_BYTES);

    auto gemm = [&](const float* A, const float* Bm, const float* bias, const float* res,
                    float* C, int M, int N, int K, int dogelu) {
        dim3 g((N + 127) / 128, (M + 127) / 128);
        tf32gemm<<<g, 256, GEMM_SMEM_BYTES>>>(A, Bm, bias, res, C, M, N, K, dogelu);
    };

    // Patch embedding
    patch_gather<<<(MP_ * D_ + 255) / 256, 256>>>(x);
    gemm(patches, patch_w, patch_b, nullptr, hp, MP_, D_, D_, 0);
    assemble<<<(M_ * D_ + 255) / 256, 256>>>(cls_token, pos_emb);

    // Transformer blocks
    for (int l = 0; l < L_; l++) {
        const size_t wo = (size_t)l * D_ * D_;
        const size_t bo = (size_t)l * D_;

        ln_kernel<<<M_, 256>>>(h, ln1_w + bo, ln1_b + bo, z);
        gemm(z, wq + wo, bq + bo, nullptr, q, M_, D_, D_, 0);
        gemm(z, wk + wo, bk + bo, nullptr, k, M_, D_, D_, 0);
        gemm(z, wv + wo, bv + bo, nullptr, v, M_, D_, D_, 0);

        attn_fused<<<dim3(4, B_ * NH_), 256, ATTN_SMEM_BYTES>>>(q, k, v, y);

        gemm(y, wy + wo, by + bo, h, h, M_, D_, D_, 0);  // residual 1

        ln_kernel<<<M_, 256>>>(h, ln2_w + bo, ln2_b + bo, z);
        gemm(z, m1w + (size_t)l * D_ * FF_, m1b + (size_t)l * FF_, nullptr, mlp, M_, FF_, D_, 1);
        gemm(mlp, m2w + (size_t)l * FF_ * D_, m2b + bo, h, h, M_, D_, FF_, 0);  // residual 2
    }

    // Head
    cls_extract<<<(B_ * D_ + 255) / 256, 256>>>();
    ln_kernel<<<B_, 256>>>(cls, hlnw, hlnb, clsln);
    gemm(clsln, hw, hb, nullptr, out, B_, NC_, D_, 0);
}